// round 5
// baseline (speedup 1.0000x reference)
#include <cuda_runtime.h>
#include <cuda_bf16.h>
#include <math_constants.h>
#include <cstdint>

// Problem constants
#define S_LEN   2048
#define DMODEL  2048
#define NHEADS  16
#define HDIM    128
#define BATCH   4
#define MROWS   (BATCH * S_LEN)   // 8192

// ---------------------------------------------------------------------------
// Scratch (device globals; no allocation in kernel_launch)
// ---------------------------------------------------------------------------
__device__ __nv_bfloat16 g_xhi[(size_t)MROWS * DMODEL];
__device__ __nv_bfloat16 g_xlo[(size_t)MROWS * DMODEL];
__device__ __nv_bfloat16 g_whi[4][(size_t)DMODEL * DMODEL];
__device__ __nv_bfloat16 g_wlo[4][(size_t)DMODEL * DMODEL];
__device__ float g_q[(size_t)BATCH * NHEADS * S_LEN * HDIM];   // [B,H,S,hd] pre-RoPE
__device__ float g_k[(size_t)BATCH * NHEADS * S_LEN * HDIM];
__device__ __nv_bfloat16 g_qhi[(size_t)BATCH * NHEADS * S_LEN * HDIM];
__device__ __nv_bfloat16 g_qlo[(size_t)BATCH * NHEADS * S_LEN * HDIM];
__device__ __nv_bfloat16 g_khi[(size_t)BATCH * NHEADS * S_LEN * HDIM];
__device__ __nv_bfloat16 g_klo[(size_t)BATCH * NHEADS * S_LEN * HDIM];
__device__ __nv_bfloat16 g_vhi[(size_t)BATCH * NHEADS * S_LEN * HDIM];
__device__ __nv_bfloat16 g_vlo[(size_t)BATCH * NHEADS * S_LEN * HDIM];
__device__ __nv_bfloat16 g_atthi[(size_t)MROWS * DMODEL];      // [B,S,D]
__device__ __nv_bfloat16 g_attlo[(size_t)MROWS * DMODEL];
__device__ float g_ct[64 * S_LEN];                              // cos[d][s]
__device__ float g_st[64 * S_LEN];                              // sin[d][s]

// ---------------------------------------------------------------------------
// PTX helpers
// ---------------------------------------------------------------------------
__device__ __forceinline__ void cp16(uint32_t smem_dst, const void* gptr) {
    asm volatile("cp.async.cg.shared.global [%0], [%1], 16;"
                 :: "r"(smem_dst), "l"(__cvta_generic_to_global(gptr)) : "memory");
}
__device__ __forceinline__ void cp_commit() {
    asm volatile("cp.async.commit_group;" ::: "memory");
}
template <int N>
__device__ __forceinline__ void cp_wait() {
    asm volatile("cp.async.wait_group %0;" :: "n"(N) : "memory");
}
__device__ __forceinline__ void ldsm4(uint32_t addr, uint32_t r[4]) {
    asm volatile("ldmatrix.sync.aligned.m8n8.x4.shared.b16 {%0,%1,%2,%3}, [%4];"
                 : "=r"(r[0]), "=r"(r[1]), "=r"(r[2]), "=r"(r[3]) : "r"(addr));
}
__device__ __forceinline__ void ldsm4t(uint32_t addr, uint32_t r[4]) {
    asm volatile("ldmatrix.sync.aligned.m8n8.x4.trans.shared.b16 {%0,%1,%2,%3}, [%4];"
                 : "=r"(r[0]), "=r"(r[1]), "=r"(r[2]), "=r"(r[3]) : "r"(addr));
}
__device__ __forceinline__ void mma16816(float c[4], const uint32_t a[4],
                                         const uint32_t b0, const uint32_t b1) {
    asm volatile(
        "mma.sync.aligned.m16n8k16.row.col.f32.bf16.bf16.f32 "
        "{%0,%1,%2,%3}, {%4,%5,%6,%7}, {%8,%9}, {%0,%1,%2,%3};"
        : "+f"(c[0]), "+f"(c[1]), "+f"(c[2]), "+f"(c[3])
        : "r"(a[0]), "r"(a[1]), "r"(a[2]), "r"(a[3]), "r"(b0), "r"(b1));
}
__device__ __forceinline__ uint32_t pack_bf16x2(float x, float y) {
    __nv_bfloat162 t = __halves2bfloat162(__float2bfloat16(x), __float2bfloat16(y));
    return *reinterpret_cast<uint32_t*>(&t);
}

// ---------------------------------------------------------------------------
// Split fp32 -> bf16 (hi, lo): x
// ---------------------------------------------------------------------------
__global__ void split_x_kernel(const float4* __restrict__ src, int n4)
{
    for (int i = blockIdx.x * blockDim.x + threadIdx.x; i < n4;
         i += gridDim.x * blockDim.x) {
        float4 v = src[i];
        float f[4] = {v.x, v.y, v.z, v.w};
        __nv_bfloat16 h[4], l[4];
        #pragma unroll
        for (int j = 0; j < 4; j++) {
            h[j] = __float2bfloat16(f[j]);
            l[j] = __float2bfloat16(f[j] - __bfloat162float(h[j]));
        }
        __nv_bfloat162* hp = reinterpret_cast<__nv_bfloat162*>(g_xhi + 4 * (size_t)i);
        __nv_bfloat162* lp = reinterpret_cast<__nv_bfloat162*>(g_xlo + 4 * (size_t)i);
        hp[0] = __halves2bfloat162(h[0], h[1]);
        hp[1] = __halves2bfloat162(h[2], h[3]);
        lp[0] = __halves2bfloat162(l[0], l[1]);
        lp[1] = __halves2bfloat162(l[2], l[3]);
    }
}

// Fused weight splits (blockIdx.y selects the weight)
__global__ void split_w_kernel(const float4* __restrict__ w0,
                               const float4* __restrict__ w1,
                               const float4* __restrict__ w2,
                               const float4* __restrict__ w3, int n4)
{
    const int which = blockIdx.y;
    const float4* src = (which == 0) ? w0 : (which == 1) ? w1 : (which == 2) ? w2 : w3;
    __nv_bfloat16* hi = g_whi[which];
    __nv_bfloat16* lo = g_wlo[which];

    for (int i = blockIdx.x * blockDim.x + threadIdx.x; i < n4;
         i += gridDim.x * blockDim.x) {
        float4 v = src[i];
        float f[4] = {v.x, v.y, v.z, v.w};
        __nv_bfloat16 h[4], l[4];
        #pragma unroll
        for (int j = 0; j < 4; j++) {
            h[j] = __float2bfloat16(f[j]);
            l[j] = __float2bfloat16(f[j] - __bfloat162float(h[j]));
        }
        __nv_bfloat162* hp = reinterpret_cast<__nv_bfloat162*>(hi + 4 * (size_t)i);
        __nv_bfloat162* lp = reinterpret_cast<__nv_bfloat162*>(lo + 4 * (size_t)i);
        hp[0] = __halves2bfloat162(h[0], h[1]);
        hp[1] = __halves2bfloat162(h[2], h[3]);
        lp[0] = __halves2bfloat162(l[0], l[1]);
        lp[1] = __halves2bfloat162(l[2], l[3]);
    }
}

// ---------------------------------------------------------------------------
// RoPE cos/sin tables: g_ct[d*2048+s], d in [0,64)
// ---------------------------------------------------------------------------
__global__ void rope_tab_kernel()
{
    int i = blockIdx.x * blockDim.x + threadIdx.x;
    if (i >= 64 * S_LEN) return;
    int d = i >> 11, s = i & 2047;
    float invf = (float)exp2(-(double)d * 0.20762050593045952);  // log2(1e4)/64
    float th = (float)s * invf;
    float c, sn;
    sincosf(th, &sn, &c);
    g_ct[i] = c;
    g_st[i] = sn;
}

// ---------------------------------------------------------------------------
// RoPE over g_q, g_k -> bf16 hi/lo  ([B,H,S,hd], pair (d, d+64))
// ---------------------------------------------------------------------------
__global__ void rope_apply_kernel()
{
    const int total = BATCH * NHEADS * S_LEN * 64;
    int i = blockIdx.x * blockDim.x + threadIdx.x;
    if (i >= total) return;
    int d = i & 63;
    int rs = i >> 6;            // flat (b,h,s)
    int s = rs & 2047;
    size_t base = (size_t)rs * HDIM;
    float c  = g_ct[d * S_LEN + s];
    float sn = g_st[d * S_LEN + s];

    float qlo = g_q[base + d], qhi = g_q[base + d + 64];
    float q0 = qlo * c - qhi * sn;
    float q1 = qhi * c + qlo * sn;
    __nv_bfloat16 h;
    h = __float2bfloat16(q0); g_qhi[base + d] = h;
    g_qlo[base + d] = __float2bfloat16(q0 - __bfloat162float(h));
    h = __float2bfloat16(q1); g_qhi[base + d + 64] = h;
    g_qlo[base + d + 64] = __float2bfloat16(q1 - __bfloat162float(h));

    float klo = g_k[base + d], khi = g_k[base + d + 64];
    float k0 = klo * c - khi * sn;
    float k1 = khi * c + klo * sn;
    h = __float2bfloat16(k0); g_khi[base + d] = h;
    g_klo[base + d] = __float2bfloat16(k0 - __bfloat162float(h));
    h = __float2bfloat16(k1); g_khi[base + d + 64] = h;
    g_klo[base + d + 64] = __float2bfloat16(k1 - __bfloat162float(h));
}

// ---------------------------------------------------------------------------
// HMMA GEMM v2: tile 128x256, BK=64, 8 warps (2m x 4n), warp tile 64x64.
// 3-product bf16 split. mode: -1 => use blockIdx.z (0=Q,1=K,2=V), 3 => Wo.
// smem/stage: Ahi 16K | Alo 16K | Bhi 32K | Blo 32K = 96KB, 2 stages = 192KB
// ---------------------------------------------------------------------------
#define GM_BM 128
#define GM_BN 256
#define GM_BK 64
#define GM_NIT (DMODEL / GM_BK)          // 32
#define GM_AHI 0
#define GM_ALO 16384
#define GM_BHI 32768
#define GM_BLO 65536
#define GM_STAGE 98304
#define GM_SMEM (2 * GM_STAGE)           // 192KB

__device__ __forceinline__ void gm_load_stage(
    uint32_t t0, int kt, int m0, int n0, int tid,
    const __nv_bfloat16* __restrict__ Ah, const __nv_bfloat16* __restrict__ Al,
    const __nv_bfloat16* __restrict__ Bh, const __nv_bfloat16* __restrict__ Bl)
{
    const int k0 = kt * GM_BK;
    #pragma unroll
    for (int i = 0; i < 4; i++) {
        int lin = tid + i * 256;
        int row = lin >> 3, ch = lin & 7;
        uint32_t soff = (uint32_t)(row * 128 + ((ch ^ (row & 7)) << 4));
        size_t ga = (size_t)(m0 + row) * DMODEL + k0 + ch * 8;
        cp16(t0 + GM_AHI + soff, Ah + ga);
        cp16(t0 + GM_ALO + soff, Al + ga);
    }
    #pragma unroll
    for (int i = 0; i < 8; i++) {
        int lin = tid + i * 256;
        int row = lin >> 3, ch = lin & 7;
        uint32_t soff = (uint32_t)(row * 128 + ((ch ^ (row & 7)) << 4));
        size_t gb = (size_t)(n0 + row) * DMODEL + k0 + ch * 8;
        cp16(t0 + GM_BHI + soff, Bh + gb);
        cp16(t0 + GM_BLO + soff, Bl + gb);
    }
}

__global__ __launch_bounds__(256, 1)
void gemm_hmma(float* __restrict__ Dout, int mode_in)
{
    extern __shared__ char smraw[];
    const uint32_t sbase = (uint32_t)__cvta_generic_to_shared(smraw);
    const int tid  = threadIdx.x;
    const int warp = tid >> 5;
    const int lane = tid & 31;
    const int m0 = blockIdx.y * GM_BM;
    const int n0 = blockIdx.x * GM_BN;
    const int mode = (mode_in < 0) ? (int)blockIdx.z : mode_in;

    const __nv_bfloat16 *Ah, *Al;
    if (mode == 3) { Ah = g_atthi; Al = g_attlo; }
    else           { Ah = g_xhi;   Al = g_xlo; }
    const __nv_bfloat16* Bh = g_whi[mode];
    const __nv_bfloat16* Bl = g_wlo[mode];

    const int wm = warp & 1;        // 0..1
    const int wn = warp >> 1;       // 0..3
    const int quad = lane >> 3;
    const int lr   = lane & 7;

    int arow[4];
    #pragma unroll
    for (int i = 0; i < 4; i++) arow[i] = wm * 64 + i * 16 + (quad & 1) * 8 + lr;
    const int aqp = quad >> 1;
    int brow[4];
    #pragma unroll
    for (int j = 0; j < 4; j++) brow[j] = wn * 64 + j * 16 + (quad >> 1) * 8 + lr;
    const int bqp = quad & 1;

    float c[4][8][4];
    #pragma unroll
    for (int i = 0; i < 4; i++)
        #pragma unroll
        for (int j = 0; j < 8; j++)
            #pragma unroll
            for (int e = 0; e < 4; e++) c[i][j][e] = 0.f;

    gm_load_stage(sbase, 0, m0, n0, tid, Ah, Al, Bh, Bl);
    cp_commit();

    #pragma unroll 1
    for (int kt = 0; kt < GM_NIT; kt++) {
        if (kt + 1 < GM_NIT) {
            gm_load_stage(sbase + ((kt + 1) & 1) * GM_STAGE, kt + 1, m0, n0, tid,
                          Ah, Al, Bh, Bl);
            cp_commit();
            cp_wait<1>();
        } else {
            cp_wait<0>();
        }
        __syncthreads();

        const uint32_t t0 = sbase + (kt & 1) * GM_STAGE;
        #pragma unroll
        for (int s = 0; s < 4; s++) {
            uint32_t ah[4][4], al[4][4];
            #pragma unroll
            for (int i = 0; i < 4; i++) {
                uint32_t off = (uint32_t)(arow[i] * 128 +
                               (((s * 2 + aqp) ^ (arow[i] & 7)) << 4));
                ldsm4(t0 + GM_AHI + off, ah[i]);
                ldsm4(t0 + GM_ALO + off, al[i]);
            }
            uint32_t bh[8][2], bl[8][2];
            #pragma unroll
            for (int j2 = 0; j2 < 4; j2++) {
                uint32_t off = (uint32_t)(brow[j2] * 128 +
                               (((s * 2 + bqp) ^ (brow[j2] & 7)) << 4));
                uint32_t t[4];
                ldsm4(t0 + GM_BHI + off, t);
                bh[2*j2][0] = t[0]; bh[2*j2][1] = t[1];
                bh[2*j2+1][0] = t[2]; bh[2*j2+1][1] = t[3];
                ldsm4(t0 + GM_BLO + off, t);
                bl[2*j2][0] = t[0]; bl[2*j2][1] = t[1];
                bl[2*j2+1][0] = t[2]; bl[2*j2+1][1] = t[3];
            }
            #pragma unroll
            for (int i = 0; i < 4; i++)
                #pragma unroll
                for (int j = 0; j < 8; j++) {
                    mma16816(c[i][j], ah[i], bh[j][0], bh[j][1]);
                    mma16816(c[i][j], al[i], bh[j][0], bh[j][1]);
                    mma16816(c[i][j], ah[i], bl[j][0], bl[j][1]);
                }
        }
        __syncthreads();
    }

    // ---------------- epilogue ----------------
    #pragma unroll
    for (int i = 0; i < 4; i++) {
        int r0 = m0 + wm * 64 + i * 16 + (lane >> 2);
        #pragma unroll
        for (int half = 0; half < 2; half++) {
            int r = r0 + half * 8;
            int bb = r >> 11, ss = r & 2047;
            #pragma unroll
            for (int j = 0; j < 8; j++) {
                int col = n0 + wn * 64 + j * 8 + (lane & 3) * 2;
                float2 v2 = make_float2(c[i][j][half * 2], c[i][j][half * 2 + 1]);
                if (mode <= 1) {
                    float* outp = (mode == 0) ? g_q : g_k;
                    int h = col >> 7, d = col & 127;
                    size_t base = (((size_t)bb * NHEADS + h) * S_LEN + ss) * HDIM + d;
                    *(float2*)(outp + base) = v2;
                } else if (mode == 2) {
                    int h = col >> 7, d = col & 127;
                    size_t base = (((size_t)bb * NHEADS + h) * S_LEN + ss) * HDIM + d;
                    __nv_bfloat16 h0 = __float2bfloat16(v2.x);
                    __nv_bfloat16 h1 = __float2bfloat16(v2.y);
                    *(__nv_bfloat162*)(g_vhi + base) = __halves2bfloat162(h0, h1);
                    *(__nv_bfloat162*)(g_vlo + base) = __halves2bfloat162(
                        __float2bfloat16(v2.x - __bfloat162float(h0)),
                        __float2bfloat16(v2.y - __bfloat162float(h1)));
                } else {
                    *(float2*)(Dout + (size_t)r * DMODEL + col) = v2;
                }
            }
        }
    }
}

// ---------------------------------------------------------------------------
// HMMA flash attention (causal). CTA = 128 q rows x 64-key tiles, 8 warps,
// warp = 16 q rows x all 64 keys. P kept in registers. 3-product splits.
// ---------------------------------------------------------------------------
#define FQHI 0
#define FQLO 32768
#define FSTG(s) (65536 + (s) * 65536)
#define FKHI 0
#define FKLO 16384
#define FVHI 32768
#define FVLO 49152
#define FA_SMEM (65536 + 2 * 65536)   // 192KB

__device__ __forceinline__ uint32_t fswz(int row, int ch) {
    return (uint32_t)(row * 256 + ((ch >> 3) << 7) + (((ch & 7) ^ (row & 7)) << 4));
}

__global__ __launch_bounds__(256, 1)
void flash_hmma()
{
    extern __shared__ char smraw[];
    const uint32_t sb = (uint32_t)__cvta_generic_to_shared(smraw);
    const int tid  = threadIdx.x;
    const int w    = tid >> 5;
    const int lane = tid & 31;
    const int quad = lane >> 3;
    const int lr   = lane & 7;
    const int qt = 15 - blockIdx.x;        // heavy CTAs first
    const int bh = blockIdx.y;

    const __nv_bfloat16* qhib = g_qhi + (size_t)bh * S_LEN * HDIM;
    const __nv_bfloat16* qlob = g_qlo + (size_t)bh * S_LEN * HDIM;
    const __nv_bfloat16* khib = g_khi + (size_t)bh * S_LEN * HDIM;
    const __nv_bfloat16* klob = g_klo + (size_t)bh * S_LEN * HDIM;
    const __nv_bfloat16* vhib = g_vhi + (size_t)bh * S_LEN * HDIM;
    const __nv_bfloat16* vlob = g_vlo + (size_t)bh * S_LEN * HDIM;

    #pragma unroll
    for (int i = 0; i < 8; i++) {
        int lin = tid + i * 256;
        int row = lin >> 4, ch = lin & 15;
        uint32_t so = fswz(row, ch);
        size_t go = (size_t)(qt * 128 + row) * HDIM + ch * 8;
        cp16(sb + FQHI + so, qhib + go);
        cp16(sb + FQLO + so, qlob + go);
    }
    cp_commit();

    const int nkt = 2 * qt + 2;

    {
        const uint32_t t0 = sb + FSTG(0);
        #pragma unroll
        for (int i = 0; i < 4; i++) {
            int lin = tid + i * 256;
            int row = lin >> 4, ch = lin & 15;
            uint32_t so = fswz(row, ch);
            size_t go = (size_t)row * HDIM + ch * 8;
            cp16(t0 + FKHI + so, khib + go);
            cp16(t0 + FKLO + so, klob + go);
            cp16(t0 + FVHI + so, vhib + go);
            cp16(t0 + FVLO + so, vlob + go);
        }
        cp_commit();
    }

    float o[16][4];
    #pragma unroll
    for (int i = 0; i < 16; i++)
        #pragma unroll
        for (int e = 0; e < 4; e++) o[i][e] = 0.f;
    float mi[2] = {-CUDART_INF_F, -CUDART_INF_F};
    float li[2] = {0.f, 0.f};

    const float scale = 0.08838834764831845f;
    const int ar  = 16 * w + (quad & 1) * 8 + lr;
    const int aqp = quad >> 1;
    const int krb = (quad >> 1) * 8 + lr;
    const int bqp = quad & 1;
    const int vrb = (quad & 1) * 8 + lr;
    const int vqp = quad >> 1;

    #pragma unroll 1
    for (int kt = 0; kt < nkt; kt++) {
        if (kt + 1 < nkt) {
            const uint32_t t0 = sb + FSTG((kt + 1) & 1);
            #pragma unroll
            for (int i = 0; i < 4; i++) {
                int lin = tid + i * 256;
                int row = lin >> 4, ch = lin & 15;
                uint32_t so = fswz(row, ch);
                size_t go = (size_t)((kt + 1) * 64 + row) * HDIM + ch * 8;
                cp16(t0 + FKHI + so, khib + go);
                cp16(t0 + FKLO + so, klob + go);
                cp16(t0 + FVHI + so, vhib + go);
                cp16(t0 + FVLO + so, vlob + go);
            }
            cp_commit();
            cp_wait<1>();
        } else {
            cp_wait<0>();
        }
        __syncthreads();

        const uint32_t stg = sb + FSTG(kt & 1);

        float sc[8][4];
        #pragma unroll
        for (int i = 0; i < 8; i++)
            #pragma unroll
            for (int e = 0; e < 4; e++) sc[i][e] = 0.f;

        #pragma unroll
        for (int s = 0; s < 8; s++) {
            uint32_t qh[4], ql[4];
            uint32_t ao = fswz(ar, s * 2 + aqp);
            ldsm4(sb + FQHI + ao, qh);
            ldsm4(sb + FQLO + ao, ql);
            #pragma unroll
            for (int j2 = 0; j2 < 4; j2++) {
                uint32_t bo = fswz(j2 * 16 + krb, s * 2 + bqp);
                uint32_t th[4], tl[4];
                ldsm4(stg + FKHI + bo, th);
                ldsm4(stg + FKLO + bo, tl);
                mma16816(sc[2*j2],   qh, th[0], th[1]);
                mma16816(sc[2*j2],   ql, th[0], th[1]);
                mma16816(sc[2*j2],   qh, tl[0], tl[1]);
                mma16816(sc[2*j2+1], qh, th[2], th[3]);
                mma16816(sc[2*j2+1], ql, th[2], th[3]);
                mma16816(sc[2*j2+1], qh, tl[2], tl[3]);
            }
        }

        const bool needmask = (kt * 64 + 63 > qt * 128 + 16 * w);
        const int rbase = qt * 128 + 16 * w + (lane >> 2);
        #pragma unroll
        for (int half = 0; half < 2; half++) {
            const int rg = rbase + half * 8;
            float mx = -CUDART_INF_F;
            #pragma unroll
            for (int dj = 0; dj < 8; dj++) {
                #pragma unroll
                for (int e = 0; e < 2; e++) {
                    float v = sc[dj][half * 2 + e] * scale;
                    if (needmask) {
                        int col = kt * 64 + dj * 8 + (lane & 3) * 2 + e;
                        if (col > rg) v = -CUDART_INF_F;
                    }
                    sc[dj][half * 2 + e] = v;
                    mx = fmaxf(mx, v);
                }
            }
            mx = fmaxf(mx, __shfl_xor_sync(0xffffffffu, mx, 1));
            mx = fmaxf(mx, __shfl_xor_sync(0xffffffffu, mx, 2));
            float mnew = fmaxf(mi[half], mx);
            float fct  = __expf(mi[half] - mnew);
            mi[half] = mnew;
            float ssum = 0.f;
            #pragma unroll
            for (int dj = 0; dj < 8; dj++) {
                #pragma unroll
                for (int e = 0; e < 2; e++) {
                    float p = __expf(sc[dj][half * 2 + e] - mnew);
                    sc[dj][half * 2 + e] = p;
                    ssum += p;
                }
            }
            ssum += __shfl_xor_sync(0xffffffffu, ssum, 1);
            ssum += __shfl_xor_sync(0xffffffffu, ssum, 2);
            li[half] = li[half] * fct + ssum;
            #pragma unroll
            for (int dt = 0; dt < 16; dt++) {
                o[dt][half * 2]     *= fct;
                o[dt][half * 2 + 1] *= fct;
            }
        }

        #pragma unroll
        for (int t = 0; t < 4; t++) {
            uint32_t ph[4], pl[4];
            #pragma unroll
            for (int pair = 0; pair < 2; pair++) {
                const float* sp = sc[2 * t + pair];
                #pragma unroll
                for (int hh = 0; hh < 2; hh++) {
                    float p0 = sp[hh * 2], p1 = sp[hh * 2 + 1];
                    uint32_t hi = pack_bf16x2(p0, p1);
                    __nv_bfloat162 hb = *reinterpret_cast<__nv_bfloat162*>(&hi);
                    uint32_t lo = pack_bf16x2(p0 - __bfloat162float(hb.x),
                                              p1 - __bfloat162float(hb.y));
                    ph[pair * 2 + hh] = hi;
                    pl[pair * 2 + hh] = lo;
                }
            }
            #pragma unroll
            for (int j2 = 0; j2 < 8; j2++) {
                uint32_t vo = fswz(t * 16 + vrb, j2 * 2 + vqp);
                uint32_t vh[4], vl[4];
                ldsm4t(stg + FVHI + vo, vh);
                ldsm4t(stg + FVLO + vo, vl);
                mma16816(o[2*j2],   ph, vh[0], vh[1]);
                mma16816(o[2*j2],   pl, vh[0], vh[1]);
                mma16816(o[2*j2],   ph, vl[0], vl[1]);
                mma16816(o[2*j2+1], ph, vh[2], vh[3]);
                mma16816(o[2*j2+1], pl, vh[2], vh[3]);
                mma16816(o[2*j2+1], ph, vl[2], vl[3]);
            }
        }
        __syncthreads();
    }

    const int b  = bh >> 4;
    const int hh = bh & 15;
    const float inva = 1.0f / li[0];
    const float invb = 1.0f / li[1];
    const int sa = qt * 128 + 16 * w + (lane >> 2);

    #pragma unroll
    for (int dj = 0; dj < 16; dj++) {
        int col = hh * HDIM + dj * 8 + (lane & 3) * 2;
        size_t ia = ((size_t)b * S_LEN + sa) * DMODEL + col;
        size_t ib = ((size_t)b * S_LEN + sa + 8) * DMODEL + col;
        float a0 = o[dj][0] * inva, a1 = o[dj][1] * inva;
        float b0 = o[dj][2] * invb, b1 = o[dj][3] * invb;
        __nv_bfloat16 ha0 = __float2bfloat16(a0), ha1 = __float2bfloat16(a1);
        __nv_bfloat16 hb0 = __float2bfloat16(b0), hb1 = __float2bfloat16(b1);
        *(__nv_bfloat162*)(g_atthi + ia) = __halves2bfloat162(ha0, ha1);
        *(__nv_bfloat162*)(g_attlo + ia) = __halves2bfloat162(
            __float2bfloat16(a0 - __bfloat162float(ha0)),
            __float2bfloat16(a1 - __bfloat162float(ha1)));
        *(__nv_bfloat162*)(g_atthi + ib) = __halves2bfloat162(hb0, hb1);
        *(__nv_bfloat162*)(g_attlo + ib) = __halves2bfloat162(
            __float2bfloat16(b0 - __bfloat162float(hb0)),
            __float2bfloat16(b1 - __bfloat162float(hb1)));
    }
}

// ---------------------------------------------------------------------------
// Launch
// ---------------------------------------------------------------------------
extern "C" void kernel_launch(void* const* d_in, const int* in_sizes, int n_in,
                              void* d_out, int out_size)
{
    const float* x  = (const float*)d_in[0];
    const float* Wq = (const float*)d_in[1];
    const float* Wk = (const float*)d_in[2];
    const float* Wv = (const float*)d_in[3];
    const float* Wo = (const float*)d_in[4];
    float* out = (float*)d_out;

    int n4x = MROWS * DMODEL / 4;
    int n4w = DMODEL * DMODEL / 4;
    split_x_kernel<<<2048, 256>>>((const float4*)x, n4x);
    split_w_kernel<<<dim3(1024, 4), 256>>>((const float4*)Wq, (const float4*)Wk,
                                           (const float4*)Wv, (const float4*)Wo, n4w);
    rope_tab_kernel<<<(64 * S_LEN + 255) / 256, 256>>>();

    cudaFuncSetAttribute(gemm_hmma, cudaFuncAttributeMaxDynamicSharedMemorySize, GM_SMEM);

    // fused Q/K/V projections: blockIdx.z = mode
    gemm_hmma<<<dim3(DMODEL / GM_BN, MROWS / GM_BM, 3), 256, GM_SMEM>>>(nullptr, -1);

    rope_apply_kernel<<<(BATCH * NHEADS * S_LEN * 64 + 255) / 256, 256>>>();

    cudaFuncSetAttribute(flash_hmma, cudaFuncAttributeMaxDynamicSharedMemorySize, FA_SMEM);
    flash_hmma<<<dim3(16, BATCH * NHEADS), 256, FA_SMEM>>>();

    gemm_hmma<<<dim3(DMODEL / GM_BN, MROWS / GM_BM), 256, GM_SMEM>>>(out, 3);
}

// round 6
// speedup vs baseline: 1.4401x; 1.4401x over previous
#include <cuda_runtime.h>
#include <cuda_fp16.h>
#include <math_constants.h>
#include <cstdint>

// Problem constants
#define S_LEN   2048
#define DMODEL  2048
#define NHEADS  16
#define HDIM    128
#define BATCH   4
#define MROWS   (BATCH * S_LEN)   // 8192

// ---------------------------------------------------------------------------
// Scratch (device globals; no allocation in kernel_launch)
// ---------------------------------------------------------------------------
__device__ __half g_xhi[(size_t)MROWS * DMODEL];
__device__ __half g_xlo[(size_t)MROWS * DMODEL];
__device__ __half g_wh[4][(size_t)DMODEL * DMODEL];            // weights, fp16 (hi only)
__device__ float g_q[(size_t)BATCH * NHEADS * S_LEN * HDIM];   // [B,H,S,hd] pre-RoPE
__device__ float g_k[(size_t)BATCH * NHEADS * S_LEN * HDIM];
__device__ __half g_qhi[(size_t)BATCH * NHEADS * S_LEN * HDIM];
__device__ __half g_qlo[(size_t)BATCH * NHEADS * S_LEN * HDIM];
__device__ __half g_khi[(size_t)BATCH * NHEADS * S_LEN * HDIM];
__device__ __half g_vhi[(size_t)BATCH * NHEADS * S_LEN * HDIM];
__device__ __half g_atthi[(size_t)MROWS * DMODEL];             // [B,S,D]
__device__ __half g_attlo[(size_t)MROWS * DMODEL];
__device__ float g_ct[64 * S_LEN];                              // cos[d][s]
__device__ float g_st[64 * S_LEN];                              // sin[d][s]

// ---------------------------------------------------------------------------
// PTX helpers
// ---------------------------------------------------------------------------
__device__ __forceinline__ void cp16(uint32_t smem_dst, const void* gptr) {
    asm volatile("cp.async.cg.shared.global [%0], [%1], 16;"
                 :: "r"(smem_dst), "l"(__cvta_generic_to_global(gptr)) : "memory");
}
__device__ __forceinline__ void cp_commit() {
    asm volatile("cp.async.commit_group;" ::: "memory");
}
template <int N>
__device__ __forceinline__ void cp_wait() {
    asm volatile("cp.async.wait_group %0;" :: "n"(N) : "memory");
}
__device__ __forceinline__ void ldsm4(uint32_t addr, uint32_t r[4]) {
    asm volatile("ldmatrix.sync.aligned.m8n8.x4.shared.b16 {%0,%1,%2,%3}, [%4];"
                 : "=r"(r[0]), "=r"(r[1]), "=r"(r[2]), "=r"(r[3]) : "r"(addr));
}
__device__ __forceinline__ void ldsm4t(uint32_t addr, uint32_t r[4]) {
    asm volatile("ldmatrix.sync.aligned.m8n8.x4.trans.shared.b16 {%0,%1,%2,%3}, [%4];"
                 : "=r"(r[0]), "=r"(r[1]), "=r"(r[2]), "=r"(r[3]) : "r"(addr));
}
__device__ __forceinline__ void mma16816(float c[4], const uint32_t a[4],
                                         const uint32_t b0, const uint32_t b1) {
    asm volatile(
        "mma.sync.aligned.m16n8k16.row.col.f32.f16.f16.f32 "
        "{%0,%1,%2,%3}, {%4,%5,%6,%7}, {%8,%9}, {%0,%1,%2,%3};"
        : "+f"(c[0]), "+f"(c[1]), "+f"(c[2]), "+f"(c[3])
        : "r"(a[0]), "r"(a[1]), "r"(a[2]), "r"(a[3]), "r"(b0), "r"(b1));
}
__device__ __forceinline__ uint32_t pack_h2(float x, float y) {
    __half2 t = __floats2half2_rn(x, y);
    return *reinterpret_cast<uint32_t*>(&t);
}

// ---------------------------------------------------------------------------
// Split fp32 -> fp16 (hi, lo): x
// ---------------------------------------------------------------------------
__global__ void split_x_kernel(const float4* __restrict__ src, int n4)
{
    for (int i = blockIdx.x * blockDim.x + threadIdx.x; i < n4;
         i += gridDim.x * blockDim.x) {
        float4 v = src[i];
        float f[4] = {v.x, v.y, v.z, v.w};
        __half h[4], l[4];
        #pragma unroll
        for (int j = 0; j < 4; j++) {
            h[j] = __float2half(f[j]);
            l[j] = __float2half(f[j] - __half2float(h[j]));
        }
        __half2* hp = reinterpret_cast<__half2*>(g_xhi + 4 * (size_t)i);
        __half2* lp = reinterpret_cast<__half2*>(g_xlo + 4 * (size_t)i);
        hp[0] = __halves2half2(h[0], h[1]);
        hp[1] = __halves2half2(h[2], h[3]);
        lp[0] = __halves2half2(l[0], l[1]);
        lp[1] = __halves2half2(l[2], l[3]);
    }
}

// Fused weight converts (blockIdx.y selects the weight), fp16 hi only
__global__ void split_w_kernel(const float4* __restrict__ w0,
                               const float4* __restrict__ w1,
                               const float4* __restrict__ w2,
                               const float4* __restrict__ w3, int n4)
{
    const int which = blockIdx.y;
    const float4* src = (which == 0) ? w0 : (which == 1) ? w1 : (which == 2) ? w2 : w3;
    __half* hi = g_wh[which];

    for (int i = blockIdx.x * blockDim.x + threadIdx.x; i < n4;
         i += gridDim.x * blockDim.x) {
        float4 v = src[i];
        __half2* hp = reinterpret_cast<__half2*>(hi + 4 * (size_t)i);
        hp[0] = __floats2half2_rn(v.x, v.y);
        hp[1] = __floats2half2_rn(v.z, v.w);
    }
}

// ---------------------------------------------------------------------------
// RoPE cos/sin tables: g_ct[d*2048+s], d in [0,64)
// ---------------------------------------------------------------------------
__global__ void rope_tab_kernel()
{
    int i = blockIdx.x * blockDim.x + threadIdx.x;
    if (i >= 64 * S_LEN) return;
    int d = i >> 11, s = i & 2047;
    float invf = (float)exp2(-(double)d * 0.20762050593045952);  // log2(1e4)/64
    float th = (float)s * invf;
    float c, sn;
    sincosf(th, &sn, &c);
    g_ct[i] = c;
    g_st[i] = sn;
}

// ---------------------------------------------------------------------------
// RoPE over g_q, g_k.  Q -> fp16 hi/lo (A side), K -> fp16 hi only (B side).
// ---------------------------------------------------------------------------
__global__ void rope_apply_kernel()
{
    const int total = BATCH * NHEADS * S_LEN * 64;
    int i = blockIdx.x * blockDim.x + threadIdx.x;
    if (i >= total) return;
    int d = i & 63;
    int rs = i >> 6;            // flat (b,h,s)
    int s = rs & 2047;
    size_t base = (size_t)rs * HDIM;
    float c  = g_ct[d * S_LEN + s];
    float sn = g_st[d * S_LEN + s];

    float qlo = g_q[base + d], qhi = g_q[base + d + 64];
    float q0 = qlo * c - qhi * sn;
    float q1 = qhi * c + qlo * sn;
    __half h;
    h = __float2half(q0); g_qhi[base + d] = h;
    g_qlo[base + d] = __float2half(q0 - __half2float(h));
    h = __float2half(q1); g_qhi[base + d + 64] = h;
    g_qlo[base + d + 64] = __float2half(q1 - __half2float(h));

    float klo = g_k[base + d], khi = g_k[base + d + 64];
    g_khi[base + d]      = __float2half(klo * c - khi * sn);
    g_khi[base + d + 64] = __float2half(khi * c + klo * sn);
}

// ---------------------------------------------------------------------------
// HMMA GEMM v3 (fp16, 2-product): tile 128x256, BK=64, 8 warps, warp 64x64.
// mode: -1 => blockIdx.z (0=Q,1=K,2=V), 3 => Wo.
// smem/stage: Ahi 16K | Alo 16K | Bhi 32K = 64KB, 3 stages = 192KB
// ---------------------------------------------------------------------------
#define GM_BM 128
#define GM_BN 256
#define GM_BK 64
#define GM_NIT (DMODEL / GM_BK)          // 32
#define GM_AHI 0
#define GM_ALO 16384
#define GM_BHI 32768
#define GM_STAGE 65536
#define GM_SMEM (3 * GM_STAGE)           // 192KB

__device__ __forceinline__ void gm_load_stage(
    uint32_t t0, int kt, int m0, int n0, int tid,
    const __half* __restrict__ Ah, const __half* __restrict__ Al,
    const __half* __restrict__ Bh)
{
    const int k0 = kt * GM_BK;
    #pragma unroll
    for (int i = 0; i < 4; i++) {
        int lin = tid + i * 256;
        int row = lin >> 3, ch = lin & 7;
        uint32_t soff = (uint32_t)(row * 128 + ((ch ^ (row & 7)) << 4));
        size_t ga = (size_t)(m0 + row) * DMODEL + k0 + ch * 8;
        cp16(t0 + GM_AHI + soff, Ah + ga);
        cp16(t0 + GM_ALO + soff, Al + ga);
    }
    #pragma unroll
    for (int i = 0; i < 8; i++) {
        int lin = tid + i * 256;
        int row = lin >> 3, ch = lin & 7;
        uint32_t soff = (uint32_t)(row * 128 + ((ch ^ (row & 7)) << 4));
        size_t gb = (size_t)(n0 + row) * DMODEL + k0 + ch * 8;
        cp16(t0 + GM_BHI + soff, Bh + gb);
    }
}

__global__ __launch_bounds__(256, 1)
void gemm_hmma(float* __restrict__ Dout, int mode_in)
{
    extern __shared__ char smraw[];
    const uint32_t sbase = (uint32_t)__cvta_generic_to_shared(smraw);
    const int tid  = threadIdx.x;
    const int warp = tid >> 5;
    const int lane = tid & 31;
    const int m0 = blockIdx.y * GM_BM;
    const int n0 = blockIdx.x * GM_BN;
    const int mode = (mode_in < 0) ? (int)blockIdx.z : mode_in;

    const __half *Ah, *Al;
    if (mode == 3) { Ah = g_atthi; Al = g_attlo; }
    else           { Ah = g_xhi;   Al = g_xlo; }
    const __half* Bh = g_wh[mode];

    const int wm = warp & 1;        // 0..1
    const int wn = warp >> 1;       // 0..3
    const int quad = lane >> 3;
    const int lr   = lane & 7;

    int arow[4];
    #pragma unroll
    for (int i = 0; i < 4; i++) arow[i] = wm * 64 + i * 16 + (quad & 1) * 8 + lr;
    const int aqp = quad >> 1;
    int brow[4];
    #pragma unroll
    for (int j = 0; j < 4; j++) brow[j] = wn * 64 + j * 16 + (quad >> 1) * 8 + lr;
    const int bqp = quad & 1;

    float c[4][8][4];
    #pragma unroll
    for (int i = 0; i < 4; i++)
        #pragma unroll
        for (int j = 0; j < 8; j++)
            #pragma unroll
            for (int e = 0; e < 4; e++) c[i][j][e] = 0.f;

    gm_load_stage(sbase, 0, m0, n0, tid, Ah, Al, Bh);
    cp_commit();
    gm_load_stage(sbase + GM_STAGE, 1, m0, n0, tid, Ah, Al, Bh);
    cp_commit();

    int st = 0;           // stage holding kt
    #pragma unroll 1
    for (int kt = 0; kt < GM_NIT; kt++) {
        if (kt + 2 < GM_NIT) {
            int wst = st + 2; if (wst >= 3) wst -= 3;
            gm_load_stage(sbase + wst * GM_STAGE, kt + 2, m0, n0, tid, Ah, Al, Bh);
            cp_commit();
            cp_wait<2>();
        } else if (kt + 1 < GM_NIT) {
            cp_wait<1>();
        } else {
            cp_wait<0>();
        }
        __syncthreads();

        const uint32_t t0 = sbase + st * GM_STAGE;
        #pragma unroll
        for (int s = 0; s < 4; s++) {
            uint32_t ah[4][4], al[4][4];
            #pragma unroll
            for (int i = 0; i < 4; i++) {
                uint32_t off = (uint32_t)(arow[i] * 128 +
                               (((s * 2 + aqp) ^ (arow[i] & 7)) << 4));
                ldsm4(t0 + GM_AHI + off, ah[i]);
                ldsm4(t0 + GM_ALO + off, al[i]);
            }
            uint32_t bh[8][2];
            #pragma unroll
            for (int j2 = 0; j2 < 4; j2++) {
                uint32_t off = (uint32_t)(brow[j2] * 128 +
                               (((s * 2 + bqp) ^ (brow[j2] & 7)) << 4));
                uint32_t t[4];
                ldsm4(t0 + GM_BHI + off, t);
                bh[2*j2][0] = t[0]; bh[2*j2][1] = t[1];
                bh[2*j2+1][0] = t[2]; bh[2*j2+1][1] = t[3];
            }
            #pragma unroll
            for (int i = 0; i < 4; i++)
                #pragma unroll
                for (int j = 0; j < 8; j++) {
                    mma16816(c[i][j], ah[i], bh[j][0], bh[j][1]);
                    mma16816(c[i][j], al[i], bh[j][0], bh[j][1]);
                }
        }
        __syncthreads();
        if (++st == 3) st = 0;
    }

    // ---------------- epilogue ----------------
    #pragma unroll
    for (int i = 0; i < 4; i++) {
        int r0 = m0 + wm * 64 + i * 16 + (lane >> 2);
        #pragma unroll
        for (int half = 0; half < 2; half++) {
            int r = r0 + half * 8;
            int bb = r >> 11, ss = r & 2047;
            #pragma unroll
            for (int j = 0; j < 8; j++) {
                int col = n0 + wn * 64 + j * 8 + (lane & 3) * 2;
                float2 v2 = make_float2(c[i][j][half * 2], c[i][j][half * 2 + 1]);
                if (mode <= 1) {
                    float* outp = (mode == 0) ? g_q : g_k;
                    int h = col >> 7, d = col & 127;
                    size_t base = (((size_t)bb * NHEADS + h) * S_LEN + ss) * HDIM + d;
                    *(float2*)(outp + base) = v2;
                } else if (mode == 2) {
                    int h = col >> 7, d = col & 127;
                    size_t base = (((size_t)bb * NHEADS + h) * S_LEN + ss) * HDIM + d;
                    *(__half2*)(g_vhi + base) = __floats2half2_rn(v2.x, v2.y);
                } else {
                    *(float2*)(Dout + (size_t)r * DMODEL + col) = v2;
                }
            }
        }
    }
}

// ---------------------------------------------------------------------------
// HMMA flash attention (causal, fp16 2-product). CTA = 128 q rows x 64-key
// tiles, 8 warps, warp = 16 q rows x all 64 keys. P kept in registers.
// smem: Qhi 32K | Qlo 32K | 2 stages x (Khi 16K | Vhi 16K)  = 128KB
// ---------------------------------------------------------------------------
#define FQHI 0
#define FQLO 32768
#define FSTG(s) (65536 + (s) * 32768)
#define FKHI 0
#define FVHI 16384
#define FA_SMEM (65536 + 2 * 32768)   // 128KB

__device__ __forceinline__ uint32_t fswz(int row, int ch) {
    return (uint32_t)(row * 256 + ((ch >> 3) << 7) + (((ch & 7) ^ (row & 7)) << 4));
}

__global__ __launch_bounds__(256, 1)
void flash_hmma()
{
    extern __shared__ char smraw[];
    const uint32_t sb = (uint32_t)__cvta_generic_to_shared(smraw);
    const int tid  = threadIdx.x;
    const int w    = tid >> 5;
    const int lane = tid & 31;
    const int quad = lane >> 3;
    const int lr   = lane & 7;
    const int qt = 15 - blockIdx.x;        // heavy CTAs first
    const int bh = blockIdx.y;

    const __half* qhib = g_qhi + (size_t)bh * S_LEN * HDIM;
    const __half* qlob = g_qlo + (size_t)bh * S_LEN * HDIM;
    const __half* khib = g_khi + (size_t)bh * S_LEN * HDIM;
    const __half* vhib = g_vhi + (size_t)bh * S_LEN * HDIM;

    #pragma unroll
    for (int i = 0; i < 8; i++) {
        int lin = tid + i * 256;
        int row = lin >> 4, ch = lin & 15;
        uint32_t so = fswz(row, ch);
        size_t go = (size_t)(qt * 128 + row) * HDIM + ch * 8;
        cp16(sb + FQHI + so, qhib + go);
        cp16(sb + FQLO + so, qlob + go);
    }
    cp_commit();

    const int nkt = 2 * qt + 2;

    {
        const uint32_t t0 = sb + FSTG(0);
        #pragma unroll
        for (int i = 0; i < 4; i++) {
            int lin = tid + i * 256;
            int row = lin >> 4, ch = lin & 15;
            uint32_t so = fswz(row, ch);
            size_t go = (size_t)row * HDIM + ch * 8;
            cp16(t0 + FKHI + so, khib + go);
            cp16(t0 + FVHI + so, vhib + go);
        }
        cp_commit();
    }

    float o[16][4];
    #pragma unroll
    for (int i = 0; i < 16; i++)
        #pragma unroll
        for (int e = 0; e < 4; e++) o[i][e] = 0.f;
    float mi[2] = {-CUDART_INF_F, -CUDART_INF_F};
    float li[2] = {0.f, 0.f};

    const float scale = 0.08838834764831845f;
    const int ar  = 16 * w + (quad & 1) * 8 + lr;
    const int aqp = quad >> 1;
    const int krb = (quad >> 1) * 8 + lr;
    const int bqp = quad & 1;
    const int vrb = (quad & 1) * 8 + lr;
    const int vqp = quad >> 1;

    #pragma unroll 1
    for (int kt = 0; kt < nkt; kt++) {
        if (kt + 1 < nkt) {
            const uint32_t t0 = sb + FSTG((kt + 1) & 1);
            #pragma unroll
            for (int i = 0; i < 4; i++) {
                int lin = tid + i * 256;
                int row = lin >> 4, ch = lin & 15;
                uint32_t so = fswz(row, ch);
                size_t go = (size_t)((kt + 1) * 64 + row) * HDIM + ch * 8;
                cp16(t0 + FKHI + so, khib + go);
                cp16(t0 + FVHI + so, vhib + go);
            }
            cp_commit();
            cp_wait<1>();
        } else {
            cp_wait<0>();
        }
        __syncthreads();

        const uint32_t stg = sb + FSTG(kt & 1);

        float sc[8][4];
        #pragma unroll
        for (int i = 0; i < 8; i++)
            #pragma unroll
            for (int e = 0; e < 4; e++) sc[i][e] = 0.f;

        #pragma unroll
        for (int s = 0; s < 8; s++) {
            uint32_t qh[4], ql[4];
            uint32_t ao = fswz(ar, s * 2 + aqp);
            ldsm4(sb + FQHI + ao, qh);
            ldsm4(sb + FQLO + ao, ql);
            #pragma unroll
            for (int j2 = 0; j2 < 4; j2++) {
                uint32_t bo = fswz(j2 * 16 + krb, s * 2 + bqp);
                uint32_t th[4];
                ldsm4(stg + FKHI + bo, th);
                mma16816(sc[2*j2],   qh, th[0], th[1]);
                mma16816(sc[2*j2],   ql, th[0], th[1]);
                mma16816(sc[2*j2+1], qh, th[2], th[3]);
                mma16816(sc[2*j2+1], ql, th[2], th[3]);
            }
        }

        const bool needmask = (kt * 64 + 63 > qt * 128 + 16 * w);
        const int rbase = qt * 128 + 16 * w + (lane >> 2);
        #pragma unroll
        for (int half = 0; half < 2; half++) {
            const int rg = rbase + half * 8;
            float mx = -CUDART_INF_F;
            #pragma unroll
            for (int dj = 0; dj < 8; dj++) {
                #pragma unroll
                for (int e = 0; e < 2; e++) {
                    float v = sc[dj][half * 2 + e] * scale;
                    if (needmask) {
                        int col = kt * 64 + dj * 8 + (lane & 3) * 2 + e;
                        if (col > rg) v = -CUDART_INF_F;
                    }
                    sc[dj][half * 2 + e] = v;
                    mx = fmaxf(mx, v);
                }
            }
            mx = fmaxf(mx, __shfl_xor_sync(0xffffffffu, mx, 1));
            mx = fmaxf(mx, __shfl_xor_sync(0xffffffffu, mx, 2));
            float mnew = fmaxf(mi[half], mx);
            float fct  = __expf(mi[half] - mnew);
            mi[half] = mnew;
            float ssum = 0.f;
            #pragma unroll
            for (int dj = 0; dj < 8; dj++) {
                #pragma unroll
                for (int e = 0; e < 2; e++) {
                    float p = __expf(sc[dj][half * 2 + e] - mnew);
                    sc[dj][half * 2 + e] = p;
                    ssum += p;
                }
            }
            ssum += __shfl_xor_sync(0xffffffffu, ssum, 1);
            ssum += __shfl_xor_sync(0xffffffffu, ssum, 2);
            li[half] = li[half] * fct + ssum;
            #pragma unroll
            for (int dt = 0; dt < 16; dt++) {
                o[dt][half * 2]     *= fct;
                o[dt][half * 2 + 1] *= fct;
            }
        }

        #pragma unroll
        for (int t = 0; t < 4; t++) {
            uint32_t ph[4], pl[4];
            #pragma unroll
            for (int pair = 0; pair < 2; pair++) {
                const float* sp = sc[2 * t + pair];
                #pragma unroll
                for (int hh = 0; hh < 2; hh++) {
                    float p0 = sp[hh * 2], p1 = sp[hh * 2 + 1];
                    uint32_t hi = pack_h2(p0, p1);
                    __half2 hb = *reinterpret_cast<__half2*>(&hi);
                    uint32_t lo = pack_h2(p0 - __half2float(hb.x),
                                          p1 - __half2float(hb.y));
                    ph[pair * 2 + hh] = hi;
                    pl[pair * 2 + hh] = lo;
                }
            }
            #pragma unroll
            for (int j2 = 0; j2 < 8; j2++) {
                uint32_t vo = fswz(t * 16 + vrb, j2 * 2 + vqp);
                uint32_t vh[4];
                ldsm4t(stg + FVHI + vo, vh);
                mma16816(o[2*j2],   ph, vh[0], vh[1]);
                mma16816(o[2*j2],   pl, vh[0], vh[1]);
                mma16816(o[2*j2+1], ph, vh[2], vh[3]);
                mma16816(o[2*j2+1], pl, vh[2], vh[3]);
            }
        }
        __syncthreads();
    }

    const int b  = bh >> 4;
    const int hh = bh & 15;
    const float inva = 1.0f / li[0];
    const float invb = 1.0f / li[1];
    const int sa = qt * 128 + 16 * w + (lane >> 2);

    #pragma unroll
    for (int dj = 0; dj < 16; dj++) {
        int col = hh * HDIM + dj * 8 + (lane & 3) * 2;
        size_t ia = ((size_t)b * S_LEN + sa) * DMODEL + col;
        size_t ib = ((size_t)b * S_LEN + sa + 8) * DMODEL + col;
        float a0 = o[dj][0] * inva, a1 = o[dj][1] * inva;
        float b0 = o[dj][2] * invb, b1 = o[dj][3] * invb;
        __half ha0 = __float2half(a0), ha1 = __float2half(a1);
        __half hb0 = __float2half(b0), hb1 = __float2half(b1);
        *(__half2*)(g_atthi + ia) = __halves2half2(ha0, ha1);
        *(__half2*)(g_attlo + ia) = __halves2half2(
            __float2half(a0 - __half2float(ha0)),
            __float2half(a1 - __half2float(ha1)));
        *(__half2*)(g_atthi + ib) = __halves2half2(hb0, hb1);
        *(__half2*)(g_attlo + ib) = __halves2half2(
            __float2half(b0 - __half2float(hb0)),
            __float2half(b1 - __half2float(hb1)));
    }
}

// ---------------------------------------------------------------------------
// Launch
// ---------------------------------------------------------------------------
extern "C" void kernel_launch(void* const* d_in, const int* in_sizes, int n_in,
                              void* d_out, int out_size)
{
    const float* x  = (const float*)d_in[0];
    const float* Wq = (const float*)d_in[1];
    const float* Wk = (const float*)d_in[2];
    const float* Wv = (const float*)d_in[3];
    const float* Wo = (const float*)d_in[4];
    float* out = (float*)d_out;

    int n4x = MROWS * DMODEL / 4;
    int n4w = DMODEL * DMODEL / 4;
    split_x_kernel<<<2048, 256>>>((const float4*)x, n4x);
    split_w_kernel<<<dim3(1024, 4), 256>>>((const float4*)Wq, (const float4*)Wk,
                                           (const float4*)Wv, (const float4*)Wo, n4w);
    rope_tab_kernel<<<(64 * S_LEN + 255) / 256, 256>>>();

    cudaFuncSetAttribute(gemm_hmma, cudaFuncAttributeMaxDynamicSharedMemorySize, GM_SMEM);

    // fused Q/K/V projections: blockIdx.z = mode
    gemm_hmma<<<dim3(DMODEL / GM_BN, MROWS / GM_BM, 3), 256, GM_SMEM>>>(nullptr, -1);

    rope_apply_kernel<<<(BATCH * NHEADS * S_LEN * 64 + 255) / 256, 256>>>();

    cudaFuncSetAttribute(flash_hmma, cudaFuncAttributeMaxDynamicSharedMemorySize, FA_SMEM);
    flash_hmma<<<dim3(16, BATCH * NHEADS), 256, FA_SMEM>>>();

    gemm_hmma<<<dim3(DMODEL / GM_BN, MROWS / GM_BM), 256, GM_SMEM>>>(out, 3);
}

// round 7
// speedup vs baseline: 1.5023x; 1.0432x over previous
#include <cuda_runtime.h>
#include <cuda_fp16.h>
#include <math_constants.h>
#include <cstdint>

// Problem constants
#define S_LEN   2048
#define DMODEL  2048
#define NHEADS  16
#define HDIM    128
#define BATCH   4
#define MROWS   (BATCH * S_LEN)   // 8192

// ---------------------------------------------------------------------------
// Scratch (device globals; no allocation in kernel_launch)
// ---------------------------------------------------------------------------
__device__ __half g_xhi[(size_t)MROWS * DMODEL];
__device__ __half g_xlo[(size_t)MROWS * DMODEL];
__device__ __half g_wh[4][(size_t)DMODEL * DMODEL];            // weights, fp16 (hi only)
__device__ float g_q[(size_t)BATCH * NHEADS * S_LEN * HDIM];   // [B,H,S,hd] pre-RoPE
__device__ float g_k[(size_t)BATCH * NHEADS * S_LEN * HDIM];
__device__ __half g_qhi[(size_t)BATCH * NHEADS * S_LEN * HDIM];
__device__ __half g_qlo[(size_t)BATCH * NHEADS * S_LEN * HDIM];
__device__ __half g_khi[(size_t)BATCH * NHEADS * S_LEN * HDIM];
__device__ __half g_vhi[(size_t)BATCH * NHEADS * S_LEN * HDIM];
__device__ __half g_atthi[(size_t)MROWS * DMODEL];             // [B,S,D]
__device__ __half g_attlo[(size_t)MROWS * DMODEL];
__device__ float g_ct[64 * S_LEN];                              // cos[d][s]
__device__ float g_st[64 * S_LEN];                              // sin[d][s]

// ---------------------------------------------------------------------------
// PTX helpers
// ---------------------------------------------------------------------------
__device__ __forceinline__ void cp16(uint32_t smem_dst, const void* gptr) {
    asm volatile("cp.async.cg.shared.global [%0], [%1], 16;"
                 :: "r"(smem_dst), "l"(__cvta_generic_to_global(gptr)) : "memory");
}
__device__ __forceinline__ void cp_commit() {
    asm volatile("cp.async.commit_group;" ::: "memory");
}
template <int N>
__device__ __forceinline__ void cp_wait() {
    asm volatile("cp.async.wait_group %0;" :: "n"(N) : "memory");
}
__device__ __forceinline__ void ldsm4(uint32_t addr, uint32_t r[4]) {
    asm volatile("ldmatrix.sync.aligned.m8n8.x4.shared.b16 {%0,%1,%2,%3}, [%4];"
                 : "=r"(r[0]), "=r"(r[1]), "=r"(r[2]), "=r"(r[3]) : "r"(addr));
}
__device__ __forceinline__ void ldsm4t(uint32_t addr, uint32_t r[4]) {
    asm volatile("ldmatrix.sync.aligned.m8n8.x4.trans.shared.b16 {%0,%1,%2,%3}, [%4];"
                 : "=r"(r[0]), "=r"(r[1]), "=r"(r[2]), "=r"(r[3]) : "r"(addr));
}
__device__ __forceinline__ void mma16816(float c[4], const uint32_t a[4],
                                         const uint32_t b0, const uint32_t b1) {
    asm volatile(
        "mma.sync.aligned.m16n8k16.row.col.f32.f16.f16.f32 "
        "{%0,%1,%2,%3}, {%4,%5,%6,%7}, {%8,%9}, {%0,%1,%2,%3};"
        : "+f"(c[0]), "+f"(c[1]), "+f"(c[2]), "+f"(c[3])
        : "r"(a[0]), "r"(a[1]), "r"(a[2]), "r"(a[3]), "r"(b0), "r"(b1));
}
__device__ __forceinline__ uint32_t pack_h2(float x, float y) {
    __half2 t = __floats2half2_rn(x, y);
    return *reinterpret_cast<uint32_t*>(&t);
}

// ---------------------------------------------------------------------------
// Split fp32 -> fp16 (hi, lo): x
// ---------------------------------------------------------------------------
__global__ void split_x_kernel(const float4* __restrict__ src, int n4)
{
    for (int i = blockIdx.x * blockDim.x + threadIdx.x; i < n4;
         i += gridDim.x * blockDim.x) {
        float4 v = src[i];
        float f[4] = {v.x, v.y, v.z, v.w};
        __half h[4], l[4];
        #pragma unroll
        for (int j = 0; j < 4; j++) {
            h[j] = __float2half(f[j]);
            l[j] = __float2half(f[j] - __half2float(h[j]));
        }
        __half2* hp = reinterpret_cast<__half2*>(g_xhi + 4 * (size_t)i);
        __half2* lp = reinterpret_cast<__half2*>(g_xlo + 4 * (size_t)i);
        hp[0] = __halves2half2(h[0], h[1]);
        hp[1] = __halves2half2(h[2], h[3]);
        lp[0] = __halves2half2(l[0], l[1]);
        lp[1] = __halves2half2(l[2], l[3]);
    }
}

// Fused weight converts (blockIdx.y selects the weight), fp16 hi only
__global__ void split_w_kernel(const float4* __restrict__ w0,
                               const float4* __restrict__ w1,
                               const float4* __restrict__ w2,
                               const float4* __restrict__ w3, int n4)
{
    const int which = blockIdx.y;
    const float4* src = (which == 0) ? w0 : (which == 1) ? w1 : (which == 2) ? w2 : w3;
    __half* hi = g_wh[which];

    for (int i = blockIdx.x * blockDim.x + threadIdx.x; i < n4;
         i += gridDim.x * blockDim.x) {
        float4 v = src[i];
        __half2* hp = reinterpret_cast<__half2*>(hi + 4 * (size_t)i);
        hp[0] = __floats2half2_rn(v.x, v.y);
        hp[1] = __floats2half2_rn(v.z, v.w);
    }
}

// ---------------------------------------------------------------------------
// RoPE cos/sin tables: g_ct[d*2048+s], d in [0,64)
// ---------------------------------------------------------------------------
__global__ void rope_tab_kernel()
{
    int i = blockIdx.x * blockDim.x + threadIdx.x;
    if (i >= 64 * S_LEN) return;
    int d = i >> 11, s = i & 2047;
    float invf = (float)exp2(-(double)d * 0.20762050593045952);  // log2(1e4)/64
    float th = (float)s * invf;
    float c, sn;
    sincosf(th, &sn, &c);
    g_ct[i] = c;
    g_st[i] = sn;
}

// ---------------------------------------------------------------------------
// RoPE over g_q, g_k.  Q -> fp16 hi/lo (A side), K -> fp16 hi only (B side).
// ---------------------------------------------------------------------------
__global__ void rope_apply_kernel()
{
    const int total = BATCH * NHEADS * S_LEN * 64;
    int i = blockIdx.x * blockDim.x + threadIdx.x;
    if (i >= total) return;
    int d = i & 63;
    int rs = i >> 6;            // flat (b,h,s)
    int s = rs & 2047;
    size_t base = (size_t)rs * HDIM;
    float c  = g_ct[d * S_LEN + s];
    float sn = g_st[d * S_LEN + s];

    float qlo = g_q[base + d], qhi = g_q[base + d + 64];
    float q0 = qlo * c - qhi * sn;
    float q1 = qhi * c + qlo * sn;
    __half h;
    h = __float2half(q0); g_qhi[base + d] = h;
    g_qlo[base + d] = __float2half(q0 - __half2float(h));
    h = __float2half(q1); g_qhi[base + d + 64] = h;
    g_qlo[base + d + 64] = __float2half(q1 - __half2float(h));

    float klo = g_k[base + d], khi = g_k[base + d + 64];
    g_khi[base + d]      = __float2half(klo * c - khi * sn);
    g_khi[base + d + 64] = __float2half(khi * c + klo * sn);
}

// ---------------------------------------------------------------------------
// HMMA GEMM v4 (fp16, 2-product): tile 64x256, BK=64, 8 warps (2m x 4n),
// warp tile 32x64. 2 CTAs/SM. mode: -1 => blockIdx.z (0=Q,1=K,2=V), 3 => Wo.
// smem/stage: Ahi 8K | Alo 8K | Bhi 32K = 48KB, 2 stages = 96KB
// ---------------------------------------------------------------------------
#define GM_BM 64
#define GM_BN 256
#define GM_BK 64
#define GM_NIT (DMODEL / GM_BK)          // 32
#define GM_AHI 0
#define GM_ALO 8192
#define GM_BHI 16384
#define GM_STAGE 49152
#define GM_SMEM (2 * GM_STAGE)           // 96KB

__device__ __forceinline__ void gm_load_stage(
    uint32_t t0, int kt, int m0, int n0, int tid,
    const __half* __restrict__ Ah, const __half* __restrict__ Al,
    const __half* __restrict__ Bh)
{
    const int k0 = kt * GM_BK;
    #pragma unroll
    for (int i = 0; i < 2; i++) {
        int lin = tid + i * 256;
        int row = lin >> 3, ch = lin & 7;
        uint32_t soff = (uint32_t)(row * 128 + ((ch ^ (row & 7)) << 4));
        size_t ga = (size_t)(m0 + row) * DMODEL + k0 + ch * 8;
        cp16(t0 + GM_AHI + soff, Ah + ga);
        cp16(t0 + GM_ALO + soff, Al + ga);
    }
    #pragma unroll
    for (int i = 0; i < 8; i++) {
        int lin = tid + i * 256;
        int row = lin >> 3, ch = lin & 7;
        uint32_t soff = (uint32_t)(row * 128 + ((ch ^ (row & 7)) << 4));
        size_t gb = (size_t)(n0 + row) * DMODEL + k0 + ch * 8;
        cp16(t0 + GM_BHI + soff, Bh + gb);
    }
}

__global__ __launch_bounds__(256, 2)
void gemm_hmma(float* __restrict__ Dout, int mode_in)
{
    extern __shared__ char smraw[];
    const uint32_t sbase = (uint32_t)__cvta_generic_to_shared(smraw);
    const int tid  = threadIdx.x;
    const int warp = tid >> 5;
    const int lane = tid & 31;
    const int m0 = blockIdx.y * GM_BM;
    const int n0 = blockIdx.x * GM_BN;
    const int mode = (mode_in < 0) ? (int)blockIdx.z : mode_in;

    const __half *Ah, *Al;
    if (mode == 3) { Ah = g_atthi; Al = g_attlo; }
    else           { Ah = g_xhi;   Al = g_xlo; }
    const __half* Bh = g_wh[mode];

    const int wm = warp & 1;        // 0..1
    const int wn = warp >> 1;       // 0..3
    const int quad = lane >> 3;
    const int lr   = lane & 7;

    int arow[2];
    #pragma unroll
    for (int i = 0; i < 2; i++) arow[i] = wm * 32 + i * 16 + (quad & 1) * 8 + lr;
    const int aqp = quad >> 1;
    int brow[4];
    #pragma unroll
    for (int j = 0; j < 4; j++) brow[j] = wn * 64 + j * 16 + (quad >> 1) * 8 + lr;
    const int bqp = quad & 1;

    float c[2][8][4];
    #pragma unroll
    for (int i = 0; i < 2; i++)
        #pragma unroll
        for (int j = 0; j < 8; j++)
            #pragma unroll
            for (int e = 0; e < 4; e++) c[i][j][e] = 0.f;

    gm_load_stage(sbase, 0, m0, n0, tid, Ah, Al, Bh);
    cp_commit();

    #pragma unroll 1
    for (int kt = 0; kt < GM_NIT; kt++) {
        if (kt + 1 < GM_NIT) {
            gm_load_stage(sbase + ((kt + 1) & 1) * GM_STAGE, kt + 1, m0, n0, tid,
                          Ah, Al, Bh);
            cp_commit();
            cp_wait<1>();
        } else {
            cp_wait<0>();
        }
        __syncthreads();

        const uint32_t t0 = sbase + (kt & 1) * GM_STAGE;
        #pragma unroll
        for (int s = 0; s < 4; s++) {
            uint32_t ah[2][4], al[2][4];
            #pragma unroll
            for (int i = 0; i < 2; i++) {
                uint32_t off = (uint32_t)(arow[i] * 128 +
                               (((s * 2 + aqp) ^ (arow[i] & 7)) << 4));
                ldsm4(t0 + GM_AHI + off, ah[i]);
                ldsm4(t0 + GM_ALO + off, al[i]);
            }
            uint32_t bh[8][2];
            #pragma unroll
            for (int j2 = 0; j2 < 4; j2++) {
                uint32_t off = (uint32_t)(brow[j2] * 128 +
                               (((s * 2 + bqp) ^ (brow[j2] & 7)) << 4));
                uint32_t t[4];
                ldsm4(t0 + GM_BHI + off, t);
                bh[2*j2][0] = t[0]; bh[2*j2][1] = t[1];
                bh[2*j2+1][0] = t[2]; bh[2*j2+1][1] = t[3];
            }
            #pragma unroll
            for (int i = 0; i < 2; i++)
                #pragma unroll
                for (int j = 0; j < 8; j++) {
                    mma16816(c[i][j], ah[i], bh[j][0], bh[j][1]);
                    mma16816(c[i][j], al[i], bh[j][0], bh[j][1]);
                }
        }
        __syncthreads();
    }

    // ---------------- epilogue ----------------
    #pragma unroll
    for (int i = 0; i < 2; i++) {
        int r0 = m0 + wm * 32 + i * 16 + (lane >> 2);
        #pragma unroll
        for (int half = 0; half < 2; half++) {
            int r = r0 + half * 8;
            int bb = r >> 11, ss = r & 2047;
            #pragma unroll
            for (int j = 0; j < 8; j++) {
                int col = n0 + wn * 64 + j * 8 + (lane & 3) * 2;
                float2 v2 = make_float2(c[i][j][half * 2], c[i][j][half * 2 + 1]);
                if (mode <= 1) {
                    float* outp = (mode == 0) ? g_q : g_k;
                    int h = col >> 7, d = col & 127;
                    size_t base = (((size_t)bb * NHEADS + h) * S_LEN + ss) * HDIM + d;
                    *(float2*)(outp + base) = v2;
                } else if (mode == 2) {
                    int h = col >> 7, d = col & 127;
                    size_t base = (((size_t)bb * NHEADS + h) * S_LEN + ss) * HDIM + d;
                    *(__half2*)(g_vhi + base) = __floats2half2_rn(v2.x, v2.y);
                } else {
                    *(float2*)(Dout + (size_t)r * DMODEL + col) = v2;
                }
            }
        }
    }
}

// ---------------------------------------------------------------------------
// HMMA flash attention (causal, fp16 2-product). CTA = 128 q rows x 64-key
// tiles, 8 warps, warp = 16 q rows x all 64 keys. P kept in registers.
// smem: Qhi 32K | Qlo 32K | 2 stages x (Khi 16K | Vhi 16K)  = 128KB
// ---------------------------------------------------------------------------
#define FQHI 0
#define FQLO 32768
#define FSTG(s) (65536 + (s) * 32768)
#define FKHI 0
#define FVHI 16384
#define FA_SMEM (65536 + 2 * 32768)   // 128KB

__device__ __forceinline__ uint32_t fswz(int row, int ch) {
    return (uint32_t)(row * 256 + ((ch >> 3) << 7) + (((ch & 7) ^ (row & 7)) << 4));
}

__global__ __launch_bounds__(256, 1)
void flash_hmma()
{
    extern __shared__ char smraw[];
    const uint32_t sb = (uint32_t)__cvta_generic_to_shared(smraw);
    const int tid  = threadIdx.x;
    const int w    = tid >> 5;
    const int lane = tid & 31;
    const int quad = lane >> 3;
    const int lr   = lane & 7;
    const int qt = 15 - blockIdx.x;        // heavy CTAs first
    const int bh = blockIdx.y;

    const __half* qhib = g_qhi + (size_t)bh * S_LEN * HDIM;
    const __half* qlob = g_qlo + (size_t)bh * S_LEN * HDIM;
    const __half* khib = g_khi + (size_t)bh * S_LEN * HDIM;
    const __half* vhib = g_vhi + (size_t)bh * S_LEN * HDIM;

    #pragma unroll
    for (int i = 0; i < 8; i++) {
        int lin = tid + i * 256;
        int row = lin >> 4, ch = lin & 15;
        uint32_t so = fswz(row, ch);
        size_t go = (size_t)(qt * 128 + row) * HDIM + ch * 8;
        cp16(sb + FQHI + so, qhib + go);
        cp16(sb + FQLO + so, qlob + go);
    }
    cp_commit();

    const int nkt = 2 * qt + 2;

    {
        const uint32_t t0 = sb + FSTG(0);
        #pragma unroll
        for (int i = 0; i < 4; i++) {
            int lin = tid + i * 256;
            int row = lin >> 4, ch = lin & 15;
            uint32_t so = fswz(row, ch);
            size_t go = (size_t)row * HDIM + ch * 8;
            cp16(t0 + FKHI + so, khib + go);
            cp16(t0 + FVHI + so, vhib + go);
        }
        cp_commit();
    }

    float o[16][4];
    #pragma unroll
    for (int i = 0; i < 16; i++)
        #pragma unroll
        for (int e = 0; e < 4; e++) o[i][e] = 0.f;
    float mi[2] = {-CUDART_INF_F, -CUDART_INF_F};
    float li[2] = {0.f, 0.f};

    const float scale = 0.08838834764831845f;
    const int ar  = 16 * w + (quad & 1) * 8 + lr;
    const int aqp = quad >> 1;
    const int krb = (quad >> 1) * 8 + lr;
    const int bqp = quad & 1;
    const int vrb = (quad & 1) * 8 + lr;
    const int vqp = quad >> 1;

    #pragma unroll 1
    for (int kt = 0; kt < nkt; kt++) {
        if (kt + 1 < nkt) {
            const uint32_t t0 = sb + FSTG((kt + 1) & 1);
            #pragma unroll
            for (int i = 0; i < 4; i++) {
                int lin = tid + i * 256;
                int row = lin >> 4, ch = lin & 15;
                uint32_t so = fswz(row, ch);
                size_t go = (size_t)((kt + 1) * 64 + row) * HDIM + ch * 8;
                cp16(t0 + FKHI + so, khib + go);
                cp16(t0 + FVHI + so, vhib + go);
            }
            cp_commit();
            cp_wait<1>();
        } else {
            cp_wait<0>();
        }
        __syncthreads();

        const uint32_t stg = sb + FSTG(kt & 1);

        float sc[8][4];
        #pragma unroll
        for (int i = 0; i < 8; i++)
            #pragma unroll
            for (int e = 0; e < 4; e++) sc[i][e] = 0.f;

        #pragma unroll
        for (int s = 0; s < 8; s++) {
            uint32_t qh[4], ql[4];
            uint32_t ao = fswz(ar, s * 2 + aqp);
            ldsm4(sb + FQHI + ao, qh);
            ldsm4(sb + FQLO + ao, ql);
            #pragma unroll
            for (int j2 = 0; j2 < 4; j2++) {
                uint32_t bo = fswz(j2 * 16 + krb, s * 2 + bqp);
                uint32_t th[4];
                ldsm4(stg + FKHI + bo, th);
                mma16816(sc[2*j2],   qh, th[0], th[1]);
                mma16816(sc[2*j2],   ql, th[0], th[1]);
                mma16816(sc[2*j2+1], qh, th[2], th[3]);
                mma16816(sc[2*j2+1], ql, th[2], th[3]);
            }
        }

        const bool needmask = (kt * 64 + 63 > qt * 128 + 16 * w);
        const int rbase = qt * 128 + 16 * w + (lane >> 2);
        #pragma unroll
        for (int half = 0; half < 2; half++) {
            const int rg = rbase + half * 8;
            float mx = -CUDART_INF_F;
            #pragma unroll
            for (int dj = 0; dj < 8; dj++) {
                #pragma unroll
                for (int e = 0; e < 2; e++) {
                    float v = sc[dj][half * 2 + e] * scale;
                    if (needmask) {
                        int col = kt * 64 + dj * 8 + (lane & 3) * 2 + e;
                        if (col > rg) v = -CUDART_INF_F;
                    }
                    sc[dj][half * 2 + e] = v;
                    mx = fmaxf(mx, v);
                }
            }
            mx = fmaxf(mx, __shfl_xor_sync(0xffffffffu, mx, 1));
            mx = fmaxf(mx, __shfl_xor_sync(0xffffffffu, mx, 2));
            float mnew = fmaxf(mi[half], mx);
            float fct  = __expf(mi[half] - mnew);
            mi[half] = mnew;
            float ssum = 0.f;
            #pragma unroll
            for (int dj = 0; dj < 8; dj++) {
                #pragma unroll
                for (int e = 0; e < 2; e++) {
                    float p = __expf(sc[dj][half * 2 + e] - mnew);
                    sc[dj][half * 2 + e] = p;
                    ssum += p;
                }
            }
            ssum += __shfl_xor_sync(0xffffffffu, ssum, 1);
            ssum += __shfl_xor_sync(0xffffffffu, ssum, 2);
            li[half] = li[half] * fct + ssum;
            #pragma unroll
            for (int dt = 0; dt < 16; dt++) {
                o[dt][half * 2]     *= fct;
                o[dt][half * 2 + 1] *= fct;
            }
        }

        #pragma unroll
        for (int t = 0; t < 4; t++) {
            uint32_t ph[4], pl[4];
            #pragma unroll
            for (int pair = 0; pair < 2; pair++) {
                const float* sp = sc[2 * t + pair];
                #pragma unroll
                for (int hh = 0; hh < 2; hh++) {
                    float p0 = sp[hh * 2], p1 = sp[hh * 2 + 1];
                    uint32_t hi = pack_h2(p0, p1);
                    __half2 hb = *reinterpret_cast<__half2*>(&hi);
                    uint32_t lo = pack_h2(p0 - __half2float(hb.x),
                                          p1 - __half2float(hb.y));
                    ph[pair * 2 + hh] = hi;
                    pl[pair * 2 + hh] = lo;
                }
            }
            #pragma unroll
            for (int j2 = 0; j2 < 8; j2++) {
                uint32_t vo = fswz(t * 16 + vrb, j2 * 2 + vqp);
                uint32_t vh[4];
                ldsm4t(stg + FVHI + vo, vh);
                mma16816(o[2*j2],   ph, vh[0], vh[1]);
                mma16816(o[2*j2],   pl, vh[0], vh[1]);
                mma16816(o[2*j2+1], ph, vh[2], vh[3]);
                mma16816(o[2*j2+1], pl, vh[2], vh[3]);
            }
        }
        __syncthreads();
    }

    const int b  = bh >> 4;
    const int hh = bh & 15;
    const float inva = 1.0f / li[0];
    const float invb = 1.0f / li[1];
    const int sa = qt * 128 + 16 * w + (lane >> 2);

    #pragma unroll
    for (int dj = 0; dj < 16; dj++) {
        int col = hh * HDIM + dj * 8 + (lane & 3) * 2;
        size_t ia = ((size_t)b * S_LEN + sa) * DMODEL + col;
        size_t ib = ((size_t)b * S_LEN + sa + 8) * DMODEL + col;
        float a0 = o[dj][0] * inva, a1 = o[dj][1] * inva;
        float b0 = o[dj][2] * invb, b1 = o[dj][3] * invb;
        __half ha0 = __float2half(a0), ha1 = __float2half(a1);
        __half hb0 = __float2half(b0), hb1 = __float2half(b1);
        *(__half2*)(g_atthi + ia) = __halves2half2(ha0, ha1);
        *(__half2*)(g_attlo + ia) = __halves2half2(
            __float2half(a0 - __half2float(ha0)),
            __float2half(a1 - __half2float(ha1)));
        *(__half2*)(g_atthi + ib) = __halves2half2(hb0, hb1);
        *(__half2*)(g_attlo + ib) = __halves2half2(
            __float2half(b0 - __half2float(hb0)),
            __float2half(b1 - __half2float(hb1)));
    }
}

// ---------------------------------------------------------------------------
// Launch
// ---------------------------------------------------------------------------
extern "C" void kernel_launch(void* const* d_in, const int* in_sizes, int n_in,
                              void* d_out, int out_size)
{
    const float* x  = (const float*)d_in[0];
    const float* Wq = (const float*)d_in[1];
    const float* Wk = (const float*)d_in[2];
    const float* Wv = (const float*)d_in[3];
    const float* Wo = (const float*)d_in[4];
    float* out = (float*)d_out;

    int n4x = MROWS * DMODEL / 4;
    int n4w = DMODEL * DMODEL / 4;
    split_x_kernel<<<2048, 256>>>((const float4*)x, n4x);
    split_w_kernel<<<dim3(1024, 4), 256>>>((const float4*)Wq, (const float4*)Wk,
                                           (const float4*)Wv, (const float4*)Wo, n4w);
    rope_tab_kernel<<<(64 * S_LEN + 255) / 256, 256>>>();

    cudaFuncSetAttribute(gemm_hmma, cudaFuncAttributeMaxDynamicSharedMemorySize, GM_SMEM);

    // fused Q/K/V projections: blockIdx.z = mode
    gemm_hmma<<<dim3(DMODEL / GM_BN, MROWS / GM_BM, 3), 256, GM_SMEM>>>(nullptr, -1);

    rope_apply_kernel<<<(BATCH * NHEADS * S_LEN * 64 + 255) / 256, 256>>>();

    cudaFuncSetAttribute(flash_hmma, cudaFuncAttributeMaxDynamicSharedMemorySize, FA_SMEM);
    flash_hmma<<<dim3(16, BATCH * NHEADS), 256, FA_SMEM>>>();

    gemm_hmma<<<dim3(DMODEL / GM_BN, MROWS / GM_BM), 256, GM_SMEM>>>(out, 3);
}

// round 8
// speedup vs baseline: 1.6071x; 1.0698x over previous
#include <cuda_runtime.h>
#include <cuda_fp16.h>
#include <math_constants.h>
#include <cstdint>

// Problem constants
#define S_LEN   2048
#define DMODEL  2048
#define NHEADS  16
#define HDIM    128
#define BATCH   4
#define MROWS   (BATCH * S_LEN)   // 8192

// ---------------------------------------------------------------------------
// Scratch (device globals; no allocation in kernel_launch)
// ---------------------------------------------------------------------------
__device__ __half g_xhi[(size_t)MROWS * DMODEL];
__device__ __half g_xlo[(size_t)MROWS * DMODEL];
__device__ __half g_wh[4][(size_t)DMODEL * DMODEL];            // weights, fp16
__device__ float g_q[(size_t)BATCH * NHEADS * S_LEN * HDIM];   // [B,H,S,hd] pre-RoPE
__device__ float g_k[(size_t)BATCH * NHEADS * S_LEN * HDIM];
__device__ __half g_qhi[(size_t)BATCH * NHEADS * S_LEN * HDIM];
__device__ __half g_qlo[(size_t)BATCH * NHEADS * S_LEN * HDIM];
__device__ __half g_khi[(size_t)BATCH * NHEADS * S_LEN * HDIM];
__device__ __half g_vhi[(size_t)BATCH * NHEADS * S_LEN * HDIM];
__device__ __half g_atthi[(size_t)MROWS * DMODEL];             // [B,S,D]
__device__ __half g_attlo[(size_t)MROWS * DMODEL];
__device__ float g_ct[64 * S_LEN];                              // cos[d][s]
__device__ float g_st[64 * S_LEN];                              // sin[d][s]

// ---------------------------------------------------------------------------
// PTX helpers
// ---------------------------------------------------------------------------
__device__ __forceinline__ void cp16(uint32_t smem_dst, const void* gptr) {
    asm volatile("cp.async.cg.shared.global [%0], [%1], 16;"
                 :: "r"(smem_dst), "l"(__cvta_generic_to_global(gptr)) : "memory");
}
__device__ __forceinline__ void cp_commit() {
    asm volatile("cp.async.commit_group;" ::: "memory");
}
template <int N>
__device__ __forceinline__ void cp_wait() {
    asm volatile("cp.async.wait_group %0;" :: "n"(N) : "memory");
}
__device__ __forceinline__ void ldsm4(uint32_t addr, uint32_t r[4]) {
    asm volatile("ldmatrix.sync.aligned.m8n8.x4.shared.b16 {%0,%1,%2,%3}, [%4];"
                 : "=r"(r[0]), "=r"(r[1]), "=r"(r[2]), "=r"(r[3]) : "r"(addr));
}
__device__ __forceinline__ void ldsm4t(uint32_t addr, uint32_t r[4]) {
    asm volatile("ldmatrix.sync.aligned.m8n8.x4.trans.shared.b16 {%0,%1,%2,%3}, [%4];"
                 : "=r"(r[0]), "=r"(r[1]), "=r"(r[2]), "=r"(r[3]) : "r"(addr));
}
__device__ __forceinline__ void mma16816(float c[4], const uint32_t a[4],
                                         const uint32_t b0, const uint32_t b1) {
    asm volatile(
        "mma.sync.aligned.m16n8k16.row.col.f32.f16.f16.f32 "
        "{%0,%1,%2,%3}, {%4,%5,%6,%7}, {%8,%9}, {%0,%1,%2,%3};"
        : "+f"(c[0]), "+f"(c[1]), "+f"(c[2]), "+f"(c[3])
        : "r"(a[0]), "r"(a[1]), "r"(a[2]), "r"(a[3]), "r"(b0), "r"(b1));
}
__device__ __forceinline__ uint32_t pack_h2(float x, float y) {
    __half2 t = __floats2half2_rn(x, y);
    return *reinterpret_cast<uint32_t*>(&t);
}

// ---------------------------------------------------------------------------
// Split fp32 -> fp16 (hi, lo): x
// ---------------------------------------------------------------------------
__global__ void split_x_kernel(const float4* __restrict__ src, int n4)
{
    for (int i = blockIdx.x * blockDim.x + threadIdx.x; i < n4;
         i += gridDim.x * blockDim.x) {
        float4 v = src[i];
        float f[4] = {v.x, v.y, v.z, v.w};
        __half h[4], l[4];
        #pragma unroll
        for (int j = 0; j < 4; j++) {
            h[j] = __float2half(f[j]);
            l[j] = __float2half(f[j] - __half2float(h[j]));
        }
        __half2* hp = reinterpret_cast<__half2*>(g_xhi + 4 * (size_t)i);
        __half2* lp = reinterpret_cast<__half2*>(g_xlo + 4 * (size_t)i);
        hp[0] = __halves2half2(h[0], h[1]);
        hp[1] = __halves2half2(h[2], h[3]);
        lp[0] = __halves2half2(l[0], l[1]);
        lp[1] = __halves2half2(l[2], l[3]);
    }
}

// Fused weight converts (blockIdx.y selects the weight), fp16 hi only
__global__ void split_w_kernel(const float4* __restrict__ w0,
                               const float4* __restrict__ w1,
                               const float4* __restrict__ w2,
                               const float4* __restrict__ w3, int n4)
{
    const int which = blockIdx.y;
    const float4* src = (which == 0) ? w0 : (which == 1) ? w1 : (which == 2) ? w2 : w3;
    __half* hi = g_wh[which];

    for (int i = blockIdx.x * blockDim.x + threadIdx.x; i < n4;
         i += gridDim.x * blockDim.x) {
        float4 v = src[i];
        __half2* hp = reinterpret_cast<__half2*>(hi + 4 * (size_t)i);
        hp[0] = __floats2half2_rn(v.x, v.y);
        hp[1] = __floats2half2_rn(v.z, v.w);
    }
}

// ---------------------------------------------------------------------------
// RoPE cos/sin tables: g_ct[d*2048+s], d in [0,64)
// ---------------------------------------------------------------------------
__global__ void rope_tab_kernel()
{
    int i = blockIdx.x * blockDim.x + threadIdx.x;
    if (i >= 64 * S_LEN) return;
    int d = i >> 11, s = i & 2047;
    float invf = (float)exp2(-(double)d * 0.20762050593045952);  // log2(1e4)/64
    float th = (float)s * invf;
    float c, sn;
    sincosf(th, &sn, &c);
    g_ct[i] = c;
    g_st[i] = sn;
}

// ---------------------------------------------------------------------------
// RoPE over g_q, g_k.  Q -> fp16 hi/lo (A side), K -> fp16 hi only (B side).
// ---------------------------------------------------------------------------
__global__ void rope_apply_kernel()
{
    const int total = BATCH * NHEADS * S_LEN * 64;
    int i = blockIdx.x * blockDim.x + threadIdx.x;
    if (i >= total) return;
    int d = i & 63;
    int rs = i >> 6;            // flat (b,h,s)
    int s = rs & 2047;
    size_t base = (size_t)rs * HDIM;
    float c  = g_ct[d * S_LEN + s];
    float sn = g_st[d * S_LEN + s];

    float qlo = g_q[base + d], qhi = g_q[base + d + 64];
    float q0 = qlo * c - qhi * sn;
    float q1 = qhi * c + qlo * sn;
    __half h;
    h = __float2half(q0); g_qhi[base + d] = h;
    g_qlo[base + d] = __float2half(q0 - __half2float(h));
    h = __float2half(q1); g_qhi[base + d + 64] = h;
    g_qlo[base + d + 64] = __float2half(q1 - __half2float(h));

    float klo = g_k[base + d], khi = g_k[base + d + 64];
    g_khi[base + d]      = __float2half(klo * c - khi * sn);
    g_khi[base + d + 64] = __float2half(khi * c + klo * sn);
}

// ---------------------------------------------------------------------------
// HMMA GEMM v5 (fp16): tile 64x256, BK=64, 8 warps (2m x 4n), warp 32x64.
// 2 CTAs/SM. Products: Q (mode 0) and Wo (mode 3) use hi+lo A (2 products);
// K (1) and V (2) use hi-only A (1 product) since their outputs are rounded
// to fp16 anyway. mode_in: -1 => blockIdx.z selects 0..2; 3 => Wo.
// smem/stage: Ahi 8K | Alo 8K | Bhi 32K = 48KB, 2 stages = 96KB
// ---------------------------------------------------------------------------
#define GM_BM 64
#define GM_BN 256
#define GM_BK 64
#define GM_NIT (DMODEL / GM_BK)          // 32
#define GM_AHI 0
#define GM_ALO 8192
#define GM_BHI 16384
#define GM_STAGE 49152
#define GM_SMEM (2 * GM_STAGE)           // 96KB

__device__ __forceinline__ void gm_load_stage(
    uint32_t t0, int kt, int m0, int n0, int tid, bool twoprod,
    const __half* __restrict__ Ah, const __half* __restrict__ Al,
    const __half* __restrict__ Bh)
{
    const int k0 = kt * GM_BK;
    #pragma unroll
    for (int i = 0; i < 2; i++) {
        int lin = tid + i * 256;
        int row = lin >> 3, ch = lin & 7;
        uint32_t soff = (uint32_t)(row * 128 + ((ch ^ (row & 7)) << 4));
        size_t ga = (size_t)(m0 + row) * DMODEL + k0 + ch * 8;
        cp16(t0 + GM_AHI + soff, Ah + ga);
        if (twoprod) cp16(t0 + GM_ALO + soff, Al + ga);
    }
    #pragma unroll
    for (int i = 0; i < 8; i++) {
        int lin = tid + i * 256;
        int row = lin >> 3, ch = lin & 7;
        uint32_t soff = (uint32_t)(row * 128 + ((ch ^ (row & 7)) << 4));
        size_t gb = (size_t)(n0 + row) * DMODEL + k0 + ch * 8;
        cp16(t0 + GM_BHI + soff, Bh + gb);
    }
}

__global__ __launch_bounds__(256, 2)
void gemm_hmma(float* __restrict__ Dout, int mode_in)
{
    extern __shared__ char smraw[];
    const uint32_t sbase = (uint32_t)__cvta_generic_to_shared(smraw);
    const int tid  = threadIdx.x;
    const int warp = tid >> 5;
    const int lane = tid & 31;
    const int m0 = blockIdx.y * GM_BM;
    const int n0 = blockIdx.x * GM_BN;
    const int mode = (mode_in < 0) ? (int)blockIdx.z : mode_in;
    const bool twoprod = (mode == 0) || (mode == 3);

    const __half *Ah, *Al;
    if (mode == 3) { Ah = g_atthi; Al = g_attlo; }
    else           { Ah = g_xhi;   Al = g_xlo; }
    const __half* Bh = g_wh[mode];

    const int wm = warp & 1;        // 0..1
    const int wn = warp >> 1;       // 0..3
    const int quad = lane >> 3;
    const int lr   = lane & 7;

    int arow[2];
    #pragma unroll
    for (int i = 0; i < 2; i++) arow[i] = wm * 32 + i * 16 + (quad & 1) * 8 + lr;
    const int aqp = quad >> 1;
    int brow[4];
    #pragma unroll
    for (int j = 0; j < 4; j++) brow[j] = wn * 64 + j * 16 + (quad >> 1) * 8 + lr;
    const int bqp = quad & 1;

    float c[2][8][4];
    #pragma unroll
    for (int i = 0; i < 2; i++)
        #pragma unroll
        for (int j = 0; j < 8; j++)
            #pragma unroll
            for (int e = 0; e < 4; e++) c[i][j][e] = 0.f;

    gm_load_stage(sbase, 0, m0, n0, tid, twoprod, Ah, Al, Bh);
    cp_commit();

    #pragma unroll 1
    for (int kt = 0; kt < GM_NIT; kt++) {
        if (kt + 1 < GM_NIT) {
            gm_load_stage(sbase + ((kt + 1) & 1) * GM_STAGE, kt + 1, m0, n0, tid,
                          twoprod, Ah, Al, Bh);
            cp_commit();
            cp_wait<1>();
        } else {
            cp_wait<0>();
        }
        __syncthreads();

        const uint32_t t0 = sbase + (kt & 1) * GM_STAGE;
        #pragma unroll
        for (int s = 0; s < 4; s++) {
            uint32_t ah[2][4], al[2][4];
            #pragma unroll
            for (int i = 0; i < 2; i++) {
                uint32_t off = (uint32_t)(arow[i] * 128 +
                               (((s * 2 + aqp) ^ (arow[i] & 7)) << 4));
                ldsm4(t0 + GM_AHI + off, ah[i]);
                if (twoprod) ldsm4(t0 + GM_ALO + off, al[i]);
            }
            uint32_t bh[8][2];
            #pragma unroll
            for (int j2 = 0; j2 < 4; j2++) {
                uint32_t off = (uint32_t)(brow[j2] * 128 +
                               (((s * 2 + bqp) ^ (brow[j2] & 7)) << 4));
                uint32_t t[4];
                ldsm4(t0 + GM_BHI + off, t);
                bh[2*j2][0] = t[0]; bh[2*j2][1] = t[1];
                bh[2*j2+1][0] = t[2]; bh[2*j2+1][1] = t[3];
            }
            #pragma unroll
            for (int i = 0; i < 2; i++)
                #pragma unroll
                for (int j = 0; j < 8; j++) {
                    mma16816(c[i][j], ah[i], bh[j][0], bh[j][1]);
                    if (twoprod) mma16816(c[i][j], al[i], bh[j][0], bh[j][1]);
                }
        }
        __syncthreads();
    }

    // ---------------- epilogue ----------------
    #pragma unroll
    for (int i = 0; i < 2; i++) {
        int r0 = m0 + wm * 32 + i * 16 + (lane >> 2);
        #pragma unroll
        for (int half = 0; half < 2; half++) {
            int r = r0 + half * 8;
            int bb = r >> 11, ss = r & 2047;
            #pragma unroll
            for (int j = 0; j < 8; j++) {
                int col = n0 + wn * 64 + j * 8 + (lane & 3) * 2;
                float2 v2 = make_float2(c[i][j][half * 2], c[i][j][half * 2 + 1]);
                if (mode <= 1) {
                    float* outp = (mode == 0) ? g_q : g_k;
                    int h = col >> 7, d = col & 127;
                    size_t base = (((size_t)bb * NHEADS + h) * S_LEN + ss) * HDIM + d;
                    *(float2*)(outp + base) = v2;
                } else if (mode == 2) {
                    int h = col >> 7, d = col & 127;
                    size_t base = (((size_t)bb * NHEADS + h) * S_LEN + ss) * HDIM + d;
                    *(__half2*)(g_vhi + base) = __floats2half2_rn(v2.x, v2.y);
                } else {
                    *(float2*)(Dout + (size_t)r * DMODEL + col) = v2;
                }
            }
        }
    }
}

// ---------------------------------------------------------------------------
// HMMA flash attention (causal, fp16). QK: Q hi+lo (2 products). PV: P hi
// only (P in [0,1]; fp16 rounding error ~2^-12 relative to the row sum).
// CTA = 128 q rows x 64-key tiles, 8 warps.
// smem: Qhi 32K | Qlo 32K | 2 stages x (Khi 16K | Vhi 16K) = 128KB
// ---------------------------------------------------------------------------
#define FQHI 0
#define FQLO 32768
#define FSTG(s) (65536 + (s) * 32768)
#define FKHI 0
#define FVHI 16384
#define FA_SMEM (65536 + 2 * 32768)   // 128KB

__device__ __forceinline__ uint32_t fswz(int row, int ch) {
    return (uint32_t)(row * 256 + ((ch >> 3) << 7) + (((ch & 7) ^ (row & 7)) << 4));
}

__global__ __launch_bounds__(256, 1)
void flash_hmma()
{
    extern __shared__ char smraw[];
    const uint32_t sb = (uint32_t)__cvta_generic_to_shared(smraw);
    const int tid  = threadIdx.x;
    const int w    = tid >> 5;
    const int lane = tid & 31;
    const int quad = lane >> 3;
    const int lr   = lane & 7;
    const int qt = 15 - blockIdx.x;        // heavy CTAs first
    const int bh = blockIdx.y;

    const __half* qhib = g_qhi + (size_t)bh * S_LEN * HDIM;
    const __half* qlob = g_qlo + (size_t)bh * S_LEN * HDIM;
    const __half* khib = g_khi + (size_t)bh * S_LEN * HDIM;
    const __half* vhib = g_vhi + (size_t)bh * S_LEN * HDIM;

    #pragma unroll
    for (int i = 0; i < 8; i++) {
        int lin = tid + i * 256;
        int row = lin >> 4, ch = lin & 15;
        uint32_t so = fswz(row, ch);
        size_t go = (size_t)(qt * 128 + row) * HDIM + ch * 8;
        cp16(sb + FQHI + so, qhib + go);
        cp16(sb + FQLO + so, qlob + go);
    }
    cp_commit();

    const int nkt = 2 * qt + 2;

    {
        const uint32_t t0 = sb + FSTG(0);
        #pragma unroll
        for (int i = 0; i < 4; i++) {
            int lin = tid + i * 256;
            int row = lin >> 4, ch = lin & 15;
            uint32_t so = fswz(row, ch);
            size_t go = (size_t)row * HDIM + ch * 8;
            cp16(t0 + FKHI + so, khib + go);
            cp16(t0 + FVHI + so, vhib + go);
        }
        cp_commit();
    }

    float o[16][4];
    #pragma unroll
    for (int i = 0; i < 16; i++)
        #pragma unroll
        for (int e = 0; e < 4; e++) o[i][e] = 0.f;
    float mi[2] = {-CUDART_INF_F, -CUDART_INF_F};
    float li[2] = {0.f, 0.f};

    const float scale = 0.08838834764831845f;
    const int ar  = 16 * w + (quad & 1) * 8 + lr;
    const int aqp = quad >> 1;
    const int krb = (quad >> 1) * 8 + lr;
    const int bqp = quad & 1;
    const int vrb = (quad & 1) * 8 + lr;
    const int vqp = quad >> 1;

    #pragma unroll 1
    for (int kt = 0; kt < nkt; kt++) {
        if (kt + 1 < nkt) {
            const uint32_t t0 = sb + FSTG((kt + 1) & 1);
            #pragma unroll
            for (int i = 0; i < 4; i++) {
                int lin = tid + i * 256;
                int row = lin >> 4, ch = lin & 15;
                uint32_t so = fswz(row, ch);
                size_t go = (size_t)((kt + 1) * 64 + row) * HDIM + ch * 8;
                cp16(t0 + FKHI + so, khib + go);
                cp16(t0 + FVHI + so, vhib + go);
            }
            cp_commit();
            cp_wait<1>();
        } else {
            cp_wait<0>();
        }
        __syncthreads();

        const uint32_t stg = sb + FSTG(kt & 1);

        float sc[8][4];
        #pragma unroll
        for (int i = 0; i < 8; i++)
            #pragma unroll
            for (int e = 0; e < 4; e++) sc[i][e] = 0.f;

        #pragma unroll
        for (int s = 0; s < 8; s++) {
            uint32_t qh[4], ql[4];
            uint32_t ao = fswz(ar, s * 2 + aqp);
            ldsm4(sb + FQHI + ao, qh);
            ldsm4(sb + FQLO + ao, ql);
            #pragma unroll
            for (int j2 = 0; j2 < 4; j2++) {
                uint32_t bo = fswz(j2 * 16 + krb, s * 2 + bqp);
                uint32_t th[4];
                ldsm4(stg + FKHI + bo, th);
                mma16816(sc[2*j2],   qh, th[0], th[1]);
                mma16816(sc[2*j2],   ql, th[0], th[1]);
                mma16816(sc[2*j2+1], qh, th[2], th[3]);
                mma16816(sc[2*j2+1], ql, th[2], th[3]);
            }
        }

        const bool needmask = (kt * 64 + 63 > qt * 128 + 16 * w);
        const int rbase = qt * 128 + 16 * w + (lane >> 2);
        #pragma unroll
        for (int half = 0; half < 2; half++) {
            const int rg = rbase + half * 8;
            float mx = -CUDART_INF_F;
            #pragma unroll
            for (int dj = 0; dj < 8; dj++) {
                #pragma unroll
                for (int e = 0; e < 2; e++) {
                    float v = sc[dj][half * 2 + e] * scale;
                    if (needmask) {
                        int col = kt * 64 + dj * 8 + (lane & 3) * 2 + e;
                        if (col > rg) v = -CUDART_INF_F;
                    }
                    sc[dj][half * 2 + e] = v;
                    mx = fmaxf(mx, v);
                }
            }
            mx = fmaxf(mx, __shfl_xor_sync(0xffffffffu, mx, 1));
            mx = fmaxf(mx, __shfl_xor_sync(0xffffffffu, mx, 2));
            float mnew = fmaxf(mi[half], mx);
            float fct  = __expf(mi[half] - mnew);
            mi[half] = mnew;
            float ssum = 0.f;
            #pragma unroll
            for (int dj = 0; dj < 8; dj++) {
                #pragma unroll
                for (int e = 0; e < 2; e++) {
                    float p = __expf(sc[dj][half * 2 + e] - mnew);
                    sc[dj][half * 2 + e] = p;
                    ssum += p;
                }
            }
            ssum += __shfl_xor_sync(0xffffffffu, ssum, 1);
            ssum += __shfl_xor_sync(0xffffffffu, ssum, 2);
            li[half] = li[half] * fct + ssum;
            #pragma unroll
            for (int dt = 0; dt < 16; dt++) {
                o[dt][half * 2]     *= fct;
                o[dt][half * 2 + 1] *= fct;
            }
        }

        #pragma unroll
        for (int t = 0; t < 4; t++) {
            uint32_t ph[4];
            #pragma unroll
            for (int pair = 0; pair < 2; pair++) {
                const float* sp = sc[2 * t + pair];
                ph[pair * 2 + 0] = pack_h2(sp[0], sp[1]);
                ph[pair * 2 + 1] = pack_h2(sp[2], sp[3]);
            }
            #pragma unroll
            for (int j2 = 0; j2 < 8; j2++) {
                uint32_t vo = fswz(t * 16 + vrb, j2 * 2 + vqp);
                uint32_t vh[4];
                ldsm4t(stg + FVHI + vo, vh);
                mma16816(o[2*j2],   ph, vh[0], vh[1]);
                mma16816(o[2*j2+1], ph, vh[2], vh[3]);
            }
        }
        __syncthreads();
    }

    const int b  = bh >> 4;
    const int hh = bh & 15;
    const float inva = 1.0f / li[0];
    const float invb = 1.0f / li[1];
    const int sa = qt * 128 + 16 * w + (lane >> 2);

    #pragma unroll
    for (int dj = 0; dj < 16; dj++) {
        int col = hh * HDIM + dj * 8 + (lane & 3) * 2;
        size_t ia = ((size_t)b * S_LEN + sa) * DMODEL + col;
        size_t ib = ((size_t)b * S_LEN + sa + 8) * DMODEL + col;
        float a0 = o[dj][0] * inva, a1 = o[dj][1] * inva;
        float b0 = o[dj][2] * invb, b1 = o[dj][3] * invb;
        __half ha0 = __float2half(a0), ha1 = __float2half(a1);
        __half hb0 = __float2half(b0), hb1 = __float2half(b1);
        *(__half2*)(g_atthi + ia) = __halves2half2(ha0, ha1);
        *(__half2*)(g_attlo + ia) = __halves2half2(
            __float2half(a0 - __half2float(ha0)),
            __float2half(a1 - __half2float(ha1)));
        *(__half2*)(g_atthi + ib) = __halves2half2(hb0, hb1);
        *(__half2*)(g_attlo + ib) = __halves2half2(
            __float2half(b0 - __half2float(hb0)),
            __float2half(b1 - __half2float(hb1)));
    }
}

// ---------------------------------------------------------------------------
// Launch
// ---------------------------------------------------------------------------
extern "C" void kernel_launch(void* const* d_in, const int* in_sizes, int n_in,
                              void* d_out, int out_size)
{
    const float* x  = (const float*)d_in[0];
    const float* Wq = (const float*)d_in[1];
    const float* Wk = (const float*)d_in[2];
    const float* Wv = (const float*)d_in[3];
    const float* Wo = (const float*)d_in[4];
    float* out = (float*)d_out;

    int n4x = MROWS * DMODEL / 4;
    int n4w = DMODEL * DMODEL / 4;
    split_x_kernel<<<2048, 256>>>((const float4*)x, n4x);
    split_w_kernel<<<dim3(1024, 4), 256>>>((const float4*)Wq, (const float4*)Wk,
                                           (const float4*)Wv, (const float4*)Wo, n4w);
    rope_tab_kernel<<<(64 * S_LEN + 255) / 256, 256>>>();

    cudaFuncSetAttribute(gemm_hmma, cudaFuncAttributeMaxDynamicSharedMemorySize, GM_SMEM);

    // fused Q/K/V projections: blockIdx.z = mode
    gemm_hmma<<<dim3(DMODEL / GM_BN, MROWS / GM_BM, 3), 256, GM_SMEM>>>(nullptr, -1);

    rope_apply_kernel<<<(BATCH * NHEADS * S_LEN * 64 + 255) / 256, 256>>>();

    cudaFuncSetAttribute(flash_hmma, cudaFuncAttributeMaxDynamicSharedMemorySize, FA_SMEM);
    flash_hmma<<<dim3(16, BATCH * NHEADS), 256, FA_SMEM>>>();

    gemm_hmma<<<dim3(DMODEL / GM_BN, MROWS / GM_BM), 256, GM_SMEM>>>(out, 3);
}

// round 9
// speedup vs baseline: 1.8685x; 1.1626x over previous
#include <cuda_runtime.h>
#include <cuda_fp16.h>
#include <math_constants.h>
#include <cstdint>

// Problem constants
#define S_LEN   2048
#define DMODEL  2048
#define NHEADS  16
#define HDIM    128
#define BATCH   4
#define MROWS   (BATCH * S_LEN)   // 8192

// ---------------------------------------------------------------------------
// Scratch (device globals; no allocation in kernel_launch)
// ---------------------------------------------------------------------------
__device__ __half g_xhi[(size_t)MROWS * DMODEL];
__device__ __half g_xlo[(size_t)MROWS * DMODEL];
__device__ __half g_wh[4][(size_t)DMODEL * DMODEL];            // weights, fp16
__device__ float g_q[(size_t)BATCH * NHEADS * S_LEN * HDIM];   // [B,H,S,hd] pre-RoPE
__device__ float g_k[(size_t)BATCH * NHEADS * S_LEN * HDIM];
__device__ __half g_qhi[(size_t)BATCH * NHEADS * S_LEN * HDIM];
__device__ __half g_qlo[(size_t)BATCH * NHEADS * S_LEN * HDIM];
__device__ __half g_khi[(size_t)BATCH * NHEADS * S_LEN * HDIM];
__device__ __half g_vhi[(size_t)BATCH * NHEADS * S_LEN * HDIM];
__device__ __half g_atthi[(size_t)MROWS * DMODEL];             // [B,S,D]
__device__ __half g_attlo[(size_t)MROWS * DMODEL];
__device__ float g_ct[64 * S_LEN];                              // cos[d][s]
__device__ float g_st[64 * S_LEN];                              // sin[d][s]

// ---------------------------------------------------------------------------
// PTX helpers
// ---------------------------------------------------------------------------
__device__ __forceinline__ void cp16(uint32_t smem_dst, const void* gptr) {
    asm volatile("cp.async.cg.shared.global [%0], [%1], 16;"
                 :: "r"(smem_dst), "l"(__cvta_generic_to_global(gptr)) : "memory");
}
__device__ __forceinline__ void cp_commit() {
    asm volatile("cp.async.commit_group;" ::: "memory");
}
template <int N>
__device__ __forceinline__ void cp_wait() {
    asm volatile("cp.async.wait_group %0;" :: "n"(N) : "memory");
}
__device__ __forceinline__ void ldsm4(uint32_t addr, uint32_t r[4]) {
    asm volatile("ldmatrix.sync.aligned.m8n8.x4.shared.b16 {%0,%1,%2,%3}, [%4];"
                 : "=r"(r[0]), "=r"(r[1]), "=r"(r[2]), "=r"(r[3]) : "r"(addr));
}
__device__ __forceinline__ void ldsm4t(uint32_t addr, uint32_t r[4]) {
    asm volatile("ldmatrix.sync.aligned.m8n8.x4.trans.shared.b16 {%0,%1,%2,%3}, [%4];"
                 : "=r"(r[0]), "=r"(r[1]), "=r"(r[2]), "=r"(r[3]) : "r"(addr));
}
__device__ __forceinline__ void mma16816(float c[4], const uint32_t a[4],
                                         const uint32_t b0, const uint32_t b1) {
    asm volatile(
        "mma.sync.aligned.m16n8k16.row.col.f32.f16.f16.f32 "
        "{%0,%1,%2,%3}, {%4,%5,%6,%7}, {%8,%9}, {%0,%1,%2,%3};"
        : "+f"(c[0]), "+f"(c[1]), "+f"(c[2]), "+f"(c[3])
        : "r"(a[0]), "r"(a[1]), "r"(a[2]), "r"(a[3]), "r"(b0), "r"(b1));
}
__device__ __forceinline__ uint32_t pack_h2(float x, float y) {
    __half2 t = __floats2half2_rn(x, y);
    return *reinterpret_cast<uint32_t*>(&t);
}

// ---------------------------------------------------------------------------
// Split fp32 -> fp16 (hi, lo): x
// ---------------------------------------------------------------------------
__global__ void split_x_kernel(const float4* __restrict__ src, int n4)
{
    for (int i = blockIdx.x * blockDim.x + threadIdx.x; i < n4;
         i += gridDim.x * blockDim.x) {
        float4 v = src[i];
        float f[4] = {v.x, v.y, v.z, v.w};
        __half h[4], l[4];
        #pragma unroll
        for (int j = 0; j < 4; j++) {
            h[j] = __float2half(f[j]);
            l[j] = __float2half(f[j] - __half2float(h[j]));
        }
        __half2* hp = reinterpret_cast<__half2*>(g_xhi + 4 * (size_t)i);
        __half2* lp = reinterpret_cast<__half2*>(g_xlo + 4 * (size_t)i);
        hp[0] = __halves2half2(h[0], h[1]);
        hp[1] = __halves2half2(h[2], h[3]);
        lp[0] = __halves2half2(l[0], l[1]);
        lp[1] = __halves2half2(l[2], l[3]);
    }
}

// Fused weight converts (blockIdx.y selects the weight), fp16 hi only
__global__ void split_w_kernel(const float4* __restrict__ w0,
                               const float4* __restrict__ w1,
                               const float4* __restrict__ w2,
                               const float4* __restrict__ w3, int n4)
{
    const int which = blockIdx.y;
    const float4* src = (which == 0) ? w0 : (which == 1) ? w1 : (which == 2) ? w2 : w3;
    __half* hi = g_wh[which];

    for (int i = blockIdx.x * blockDim.x + threadIdx.x; i < n4;
         i += gridDim.x * blockDim.x) {
        float4 v = src[i];
        __half2* hp = reinterpret_cast<__half2*>(hi + 4 * (size_t)i);
        hp[0] = __floats2half2_rn(v.x, v.y);
        hp[1] = __floats2half2_rn(v.z, v.w);
    }
}

// ---------------------------------------------------------------------------
// RoPE cos/sin tables: g_ct[d*2048+s], d in [0,64)
// ---------------------------------------------------------------------------
__global__ void rope_tab_kernel()
{
    int i = blockIdx.x * blockDim.x + threadIdx.x;
    if (i >= 64 * S_LEN) return;
    int d = i >> 11, s = i & 2047;
    float invf = (float)exp2(-(double)d * 0.20762050593045952);  // log2(1e4)/64
    float th = (float)s * invf;
    float c, sn;
    sincosf(th, &sn, &c);
    g_ct[i] = c;
    g_st[i] = sn;
}

// ---------------------------------------------------------------------------
// RoPE over g_q, g_k.  Q -> fp16 hi/lo (A side), K -> fp16 hi only (B side).
// ---------------------------------------------------------------------------
__global__ void rope_apply_kernel()
{
    const int total = BATCH * NHEADS * S_LEN * 64;
    int i = blockIdx.x * blockDim.x + threadIdx.x;
    if (i >= total) return;
    int d = i & 63;
    int rs = i >> 6;            // flat (b,h,s)
    int s = rs & 2047;
    size_t base = (size_t)rs * HDIM;
    float c  = g_ct[d * S_LEN + s];
    float sn = g_st[d * S_LEN + s];

    float qlo = g_q[base + d], qhi = g_q[base + d + 64];
    float q0 = qlo * c - qhi * sn;
    float q1 = qhi * c + qlo * sn;
    __half h;
    h = __float2half(q0); g_qhi[base + d] = h;
    g_qlo[base + d] = __float2half(q0 - __half2float(h));
    h = __float2half(q1); g_qhi[base + d + 64] = h;
    g_qlo[base + d + 64] = __float2half(q1 - __half2float(h));

    float klo = g_k[base + d], khi = g_k[base + d + 64];
    g_khi[base + d]      = __float2half(klo * c - khi * sn);
    g_khi[base + d + 64] = __float2half(khi * c + klo * sn);
}

// ---------------------------------------------------------------------------
// HMMA GEMM v6 (fp16, compile-time product count): tile 64x256, BK=64,
// 8 warps (2m x 4n), warp 32x64, 2 CTAs/SM.
// TWOPROD=true:  A = hi+lo (Q projection, Wo projection)
// TWOPROD=false: A = hi only (K, V projections; outputs rounded to fp16)
// mode: 0=Q(->g_q fp32) 1=K(->g_k fp32) 2=V(->g_vhi fp16) 3=Wo(->Dout)
// KV launch: mode_in = -1 => mode = 1 + blockIdx.z.
// smem/stage: Ahi 8K | Alo 8K | Bhi 32K = 48KB, 2 stages = 96KB
// ---------------------------------------------------------------------------
#define GM_BM 64
#define GM_BN 256
#define GM_BK 64
#define GM_NIT (DMODEL / GM_BK)          // 32
#define GM_AHI 0
#define GM_ALO 8192
#define GM_BHI 16384
#define GM_STAGE 49152
#define GM_SMEM (2 * GM_STAGE)           // 96KB

template <bool TWOPROD>
__device__ __forceinline__ void gm_load_stage(
    uint32_t t0, int kt, int m0, int n0, int tid,
    const __half* __restrict__ Ah, const __half* __restrict__ Al,
    const __half* __restrict__ Bh)
{
    const int k0 = kt * GM_BK;
    #pragma unroll
    for (int i = 0; i < 2; i++) {
        int lin = tid + i * 256;
        int row = lin >> 3, ch = lin & 7;
        uint32_t soff = (uint32_t)(row * 128 + ((ch ^ (row & 7)) << 4));
        size_t ga = (size_t)(m0 + row) * DMODEL + k0 + ch * 8;
        cp16(t0 + GM_AHI + soff, Ah + ga);
        if (TWOPROD) cp16(t0 + GM_ALO + soff, Al + ga);
    }
    #pragma unroll
    for (int i = 0; i < 8; i++) {
        int lin = tid + i * 256;
        int row = lin >> 3, ch = lin & 7;
        uint32_t soff = (uint32_t)(row * 128 + ((ch ^ (row & 7)) << 4));
        size_t gb = (size_t)(n0 + row) * DMODEL + k0 + ch * 8;
        cp16(t0 + GM_BHI + soff, Bh + gb);
    }
}

template <bool TWOPROD>
__global__ __launch_bounds__(256, 2)
void gemm_hmma(float* __restrict__ Dout, int mode_in)
{
    extern __shared__ char smraw[];
    const uint32_t sbase = (uint32_t)__cvta_generic_to_shared(smraw);
    const int tid  = threadIdx.x;
    const int warp = tid >> 5;
    const int lane = tid & 31;
    const int m0 = blockIdx.y * GM_BM;
    const int n0 = blockIdx.x * GM_BN;
    const int mode = (mode_in < 0) ? (int)(1 + blockIdx.z) : mode_in;

    const __half *Ah, *Al;
    if (mode == 3) { Ah = g_atthi; Al = g_attlo; }
    else           { Ah = g_xhi;   Al = g_xlo; }
    const __half* Bh = g_wh[mode];

    const int wm = warp & 1;        // 0..1
    const int wn = warp >> 1;       // 0..3
    const int quad = lane >> 3;
    const int lr   = lane & 7;

    int arow[2];
    #pragma unroll
    for (int i = 0; i < 2; i++) arow[i] = wm * 32 + i * 16 + (quad & 1) * 8 + lr;
    const int aqp = quad >> 1;
    int brow[4];
    #pragma unroll
    for (int j = 0; j < 4; j++) brow[j] = wn * 64 + j * 16 + (quad >> 1) * 8 + lr;
    const int bqp = quad & 1;

    float c[2][8][4];
    #pragma unroll
    for (int i = 0; i < 2; i++)
        #pragma unroll
        for (int j = 0; j < 8; j++)
            #pragma unroll
            for (int e = 0; e < 4; e++) c[i][j][e] = 0.f;

    gm_load_stage<TWOPROD>(sbase, 0, m0, n0, tid, Ah, Al, Bh);
    cp_commit();

    #pragma unroll 1
    for (int kt = 0; kt < GM_NIT; kt++) {
        if (kt + 1 < GM_NIT) {
            gm_load_stage<TWOPROD>(sbase + ((kt + 1) & 1) * GM_STAGE, kt + 1,
                                   m0, n0, tid, Ah, Al, Bh);
            cp_commit();
            cp_wait<1>();
        } else {
            cp_wait<0>();
        }
        __syncthreads();

        const uint32_t t0 = sbase + (kt & 1) * GM_STAGE;
        #pragma unroll
        for (int s = 0; s < 4; s++) {
            uint32_t ah[2][4], al[2][4];
            #pragma unroll
            for (int i = 0; i < 2; i++) {
                uint32_t off = (uint32_t)(arow[i] * 128 +
                               (((s * 2 + aqp) ^ (arow[i] & 7)) << 4));
                ldsm4(t0 + GM_AHI + off, ah[i]);
                if (TWOPROD) ldsm4(t0 + GM_ALO + off, al[i]);
            }
            uint32_t bh[8][2];
            #pragma unroll
            for (int j2 = 0; j2 < 4; j2++) {
                uint32_t off = (uint32_t)(brow[j2] * 128 +
                               (((s * 2 + bqp) ^ (brow[j2] & 7)) << 4));
                uint32_t t[4];
                ldsm4(t0 + GM_BHI + off, t);
                bh[2*j2][0] = t[0]; bh[2*j2][1] = t[1];
                bh[2*j2+1][0] = t[2]; bh[2*j2+1][1] = t[3];
            }
            #pragma unroll
            for (int i = 0; i < 2; i++)
                #pragma unroll
                for (int j = 0; j < 8; j++) {
                    mma16816(c[i][j], ah[i], bh[j][0], bh[j][1]);
                    if (TWOPROD) mma16816(c[i][j], al[i], bh[j][0], bh[j][1]);
                }
        }
        __syncthreads();
    }

    // ---------------- epilogue ----------------
    #pragma unroll
    for (int i = 0; i < 2; i++) {
        int r0 = m0 + wm * 32 + i * 16 + (lane >> 2);
        #pragma unroll
        for (int half = 0; half < 2; half++) {
            int r = r0 + half * 8;
            int bb = r >> 11, ss = r & 2047;
            #pragma unroll
            for (int j = 0; j < 8; j++) {
                int col = n0 + wn * 64 + j * 8 + (lane & 3) * 2;
                float2 v2 = make_float2(c[i][j][half * 2], c[i][j][half * 2 + 1]);
                if (mode <= 1) {
                    float* outp = (mode == 0) ? g_q : g_k;
                    int h = col >> 7, d = col & 127;
                    size_t base = (((size_t)bb * NHEADS + h) * S_LEN + ss) * HDIM + d;
                    *(float2*)(outp + base) = v2;
                } else if (mode == 2) {
                    int h = col >> 7, d = col & 127;
                    size_t base = (((size_t)bb * NHEADS + h) * S_LEN + ss) * HDIM + d;
                    *(__half2*)(g_vhi + base) = __floats2half2_rn(v2.x, v2.y);
                } else {
                    *(float2*)(Dout + (size_t)r * DMODEL + col) = v2;
                }
            }
        }
    }
}

// ---------------------------------------------------------------------------
// HMMA flash attention (causal, fp16). QK: Q hi+lo (2 products). PV: P hi
// only. CTA = 128 q rows x 64-key tiles, 8 warps.
// smem: Qhi 32K | Qlo 32K | 2 stages x (Khi 16K | Vhi 16K) = 128KB
// ---------------------------------------------------------------------------
#define FQHI 0
#define FQLO 32768
#define FSTG(s) (65536 + (s) * 32768)
#define FKHI 0
#define FVHI 16384
#define FA_SMEM (65536 + 2 * 32768)   // 128KB

__device__ __forceinline__ uint32_t fswz(int row, int ch) {
    return (uint32_t)(row * 256 + ((ch >> 3) << 7) + (((ch & 7) ^ (row & 7)) << 4));
}

__global__ __launch_bounds__(256, 1)
void flash_hmma()
{
    extern __shared__ char smraw[];
    const uint32_t sb = (uint32_t)__cvta_generic_to_shared(smraw);
    const int tid  = threadIdx.x;
    const int w    = tid >> 5;
    const int lane = tid & 31;
    const int quad = lane >> 3;
    const int lr   = lane & 7;
    const int qt = 15 - blockIdx.x;        // heavy CTAs first
    const int bh = blockIdx.y;

    const __half* qhib = g_qhi + (size_t)bh * S_LEN * HDIM;
    const __half* qlob = g_qlo + (size_t)bh * S_LEN * HDIM;
    const __half* khib = g_khi + (size_t)bh * S_LEN * HDIM;
    const __half* vhib = g_vhi + (size_t)bh * S_LEN * HDIM;

    #pragma unroll
    for (int i = 0; i < 8; i++) {
        int lin = tid + i * 256;
        int row = lin >> 4, ch = lin & 15;
        uint32_t so = fswz(row, ch);
        size_t go = (size_t)(qt * 128 + row) * HDIM + ch * 8;
        cp16(sb + FQHI + so, qhib + go);
        cp16(sb + FQLO + so, qlob + go);
    }
    cp_commit();

    const int nkt = 2 * qt + 2;

    {
        const uint32_t t0 = sb + FSTG(0);
        #pragma unroll
        for (int i = 0; i < 4; i++) {
            int lin = tid + i * 256;
            int row = lin >> 4, ch = lin & 15;
            uint32_t so = fswz(row, ch);
            size_t go = (size_t)row * HDIM + ch * 8;
            cp16(t0 + FKHI + so, khib + go);
            cp16(t0 + FVHI + so, vhib + go);
        }
        cp_commit();
    }

    float o[16][4];
    #pragma unroll
    for (int i = 0; i < 16; i++)
        #pragma unroll
        for (int e = 0; e < 4; e++) o[i][e] = 0.f;
    float mi[2] = {-CUDART_INF_F, -CUDART_INF_F};
    float li[2] = {0.f, 0.f};

    const float scale = 0.08838834764831845f;
    const int ar  = 16 * w + (quad & 1) * 8 + lr;
    const int aqp = quad >> 1;
    const int krb = (quad >> 1) * 8 + lr;
    const int bqp = quad & 1;
    const int vrb = (quad & 1) * 8 + lr;
    const int vqp = quad >> 1;

    #pragma unroll 1
    for (int kt = 0; kt < nkt; kt++) {
        if (kt + 1 < nkt) {
            const uint32_t t0 = sb + FSTG((kt + 1) & 1);
            #pragma unroll
            for (int i = 0; i < 4; i++) {
                int lin = tid + i * 256;
                int row = lin >> 4, ch = lin & 15;
                uint32_t so = fswz(row, ch);
                size_t go = (size_t)((kt + 1) * 64 + row) * HDIM + ch * 8;
                cp16(t0 + FKHI + so, khib + go);
                cp16(t0 + FVHI + so, vhib + go);
            }
            cp_commit();
            cp_wait<1>();
        } else {
            cp_wait<0>();
        }
        __syncthreads();

        const uint32_t stg = sb + FSTG(kt & 1);

        float sc[8][4];
        #pragma unroll
        for (int i = 0; i < 8; i++)
            #pragma unroll
            for (int e = 0; e < 4; e++) sc[i][e] = 0.f;

        #pragma unroll
        for (int s = 0; s < 8; s++) {
            uint32_t qh[4], ql[4];
            uint32_t ao = fswz(ar, s * 2 + aqp);
            ldsm4(sb + FQHI + ao, qh);
            ldsm4(sb + FQLO + ao, ql);
            #pragma unroll
            for (int j2 = 0; j2 < 4; j2++) {
                uint32_t bo = fswz(j2 * 16 + krb, s * 2 + bqp);
                uint32_t th[4];
                ldsm4(stg + FKHI + bo, th);
                mma16816(sc[2*j2],   qh, th[0], th[1]);
                mma16816(sc[2*j2],   ql, th[0], th[1]);
                mma16816(sc[2*j2+1], qh, th[2], th[3]);
                mma16816(sc[2*j2+1], ql, th[2], th[3]);
            }
        }

        const bool needmask = (kt * 64 + 63 > qt * 128 + 16 * w);
        const int rbase = qt * 128 + 16 * w + (lane >> 2);
        #pragma unroll
        for (int half = 0; half < 2; half++) {
            const int rg = rbase + half * 8;
            float mx = -CUDART_INF_F;
            #pragma unroll
            for (int dj = 0; dj < 8; dj++) {
                #pragma unroll
                for (int e = 0; e < 2; e++) {
                    float v = sc[dj][half * 2 + e] * scale;
                    if (needmask) {
                        int col = kt * 64 + dj * 8 + (lane & 3) * 2 + e;
                        if (col > rg) v = -CUDART_INF_F;
                    }
                    sc[dj][half * 2 + e] = v;
                    mx = fmaxf(mx, v);
                }
            }
            mx = fmaxf(mx, __shfl_xor_sync(0xffffffffu, mx, 1));
            mx = fmaxf(mx, __shfl_xor_sync(0xffffffffu, mx, 2));
            float mnew = fmaxf(mi[half], mx);
            float fct  = __expf(mi[half] - mnew);
            mi[half] = mnew;
            float ssum = 0.f;
            #pragma unroll
            for (int dj = 0; dj < 8; dj++) {
                #pragma unroll
                for (int e = 0; e < 2; e++) {
                    float p = __expf(sc[dj][half * 2 + e] - mnew);
                    sc[dj][half * 2 + e] = p;
                    ssum += p;
                }
            }
            ssum += __shfl_xor_sync(0xffffffffu, ssum, 1);
            ssum += __shfl_xor_sync(0xffffffffu, ssum, 2);
            li[half] = li[half] * fct + ssum;
            #pragma unroll
            for (int dt = 0; dt < 16; dt++) {
                o[dt][half * 2]     *= fct;
                o[dt][half * 2 + 1] *= fct;
            }
        }

        #pragma unroll
        for (int t = 0; t < 4; t++) {
            uint32_t ph[4];
            #pragma unroll
            for (int pair = 0; pair < 2; pair++) {
                const float* sp = sc[2 * t + pair];
                ph[pair * 2 + 0] = pack_h2(sp[0], sp[1]);
                ph[pair * 2 + 1] = pack_h2(sp[2], sp[3]);
            }
            #pragma unroll
            for (int j2 = 0; j2 < 8; j2++) {
                uint32_t vo = fswz(t * 16 + vrb, j2 * 2 + vqp);
                uint32_t vh[4];
                ldsm4t(stg + FVHI + vo, vh);
                mma16816(o[2*j2],   ph, vh[0], vh[1]);
                mma16816(o[2*j2+1], ph, vh[2], vh[3]);
            }
        }
        __syncthreads();
    }

    const int b  = bh >> 4;
    const int hh = bh & 15;
    const float inva = 1.0f / li[0];
    const float invb = 1.0f / li[1];
    const int sa = qt * 128 + 16 * w + (lane >> 2);

    #pragma unroll
    for (int dj = 0; dj < 16; dj++) {
        int col = hh * HDIM + dj * 8 + (lane & 3) * 2;
        size_t ia = ((size_t)b * S_LEN + sa) * DMODEL + col;
        size_t ib = ((size_t)b * S_LEN + sa + 8) * DMODEL + col;
        float a0 = o[dj][0] * inva, a1 = o[dj][1] * inva;
        float b0 = o[dj][2] * invb, b1 = o[dj][3] * invb;
        __half ha0 = __float2half(a0), ha1 = __float2half(a1);
        __half hb0 = __float2half(b0), hb1 = __float2half(b1);
        *(__half2*)(g_atthi + ia) = __halves2half2(ha0, ha1);
        *(__half2*)(g_attlo + ia) = __halves2half2(
            __float2half(a0 - __half2float(ha0)),
            __float2half(a1 - __half2float(ha1)));
        *(__half2*)(g_atthi + ib) = __halves2half2(hb0, hb1);
        *(__half2*)(g_attlo + ib) = __halves2half2(
            __float2half(b0 - __half2float(hb0)),
            __float2half(b1 - __half2float(hb1)));
    }
}

// ---------------------------------------------------------------------------
// Launch
// ---------------------------------------------------------------------------
extern "C" void kernel_launch(void* const* d_in, const int* in_sizes, int n_in,
                              void* d_out, int out_size)
{
    const float* x  = (const float*)d_in[0];
    const float* Wq = (const float*)d_in[1];
    const float* Wk = (const float*)d_in[2];
    const float* Wv = (const float*)d_in[3];
    const float* Wo = (const float*)d_in[4];
    float* out = (float*)d_out;

    int n4x = MROWS * DMODEL / 4;
    int n4w = DMODEL * DMODEL / 4;
    split_x_kernel<<<2048, 256>>>((const float4*)x, n4x);
    split_w_kernel<<<dim3(1024, 4), 256>>>((const float4*)Wq, (const float4*)Wk,
                                           (const float4*)Wv, (const float4*)Wo, n4w);
    rope_tab_kernel<<<(64 * S_LEN + 255) / 256, 256>>>();

    cudaFuncSetAttribute(gemm_hmma<true>,
                         cudaFuncAttributeMaxDynamicSharedMemorySize, GM_SMEM);
    cudaFuncSetAttribute(gemm_hmma<false>,
                         cudaFuncAttributeMaxDynamicSharedMemorySize, GM_SMEM);

    dim3 gblk(DMODEL / GM_BN, MROWS / GM_BM);       // 8 x 128

    // Q projection (2-product), K/V fused (1-product, z: 0->K, 1->V)
    gemm_hmma<true><<<gblk, 256, GM_SMEM>>>(nullptr, 0);
    gemm_hmma<false><<<dim3(gblk.x, gblk.y, 2), 256, GM_SMEM>>>(nullptr, -1);

    rope_apply_kernel<<<(BATCH * NHEADS * S_LEN * 64 + 255) / 256, 256>>>();

    cudaFuncSetAttribute(flash_hmma, cudaFuncAttributeMaxDynamicSharedMemorySize, FA_SMEM);
    flash_hmma<<<dim3(16, BATCH * NHEADS), 256, FA_SMEM>>>();

    gemm_hmma<true><<<gblk, 256, GM_SMEM>>>(out, 3);   // output projection
}

// round 10
// speedup vs baseline: 2.3293x; 1.2466x over previous
#include <cuda_runtime.h>
#include <cuda_fp16.h>
#include <math_constants.h>
#include <cstdint>

// Problem constants
#define S_LEN   2048
#define DMODEL  2048
#define NHEADS  16
#define HDIM    128
#define BATCH   4
#define MROWS   (BATCH * S_LEN)   // 8192

// ---------------------------------------------------------------------------
// Scratch (device globals; no allocation in kernel_launch)
// ---------------------------------------------------------------------------
__device__ __half g_xh[(size_t)MROWS * DMODEL];                // x, fp16
__device__ __half g_wh[4][(size_t)DMODEL * DMODEL];            // weights, fp16
__device__ float g_q[(size_t)BATCH * NHEADS * S_LEN * HDIM];   // [B,H,S,hd] pre-RoPE
__device__ float g_k[(size_t)BATCH * NHEADS * S_LEN * HDIM];
__device__ __half g_qhi[(size_t)BATCH * NHEADS * S_LEN * HDIM];
__device__ __half g_qlo[(size_t)BATCH * NHEADS * S_LEN * HDIM];
__device__ __half g_khi[(size_t)BATCH * NHEADS * S_LEN * HDIM];
__device__ __half g_vhi[(size_t)BATCH * NHEADS * S_LEN * HDIM];
__device__ __half g_atth[(size_t)MROWS * DMODEL];              // [B,S,D]
__device__ float g_ct[64 * S_LEN];                              // cos[d][s]
__device__ float g_st[64 * S_LEN];                              // sin[d][s]

// ---------------------------------------------------------------------------
// PTX helpers
// ---------------------------------------------------------------------------
__device__ __forceinline__ void cp16(uint32_t smem_dst, const void* gptr) {
    asm volatile("cp.async.cg.shared.global [%0], [%1], 16;"
                 :: "r"(smem_dst), "l"(__cvta_generic_to_global(gptr)) : "memory");
}
__device__ __forceinline__ void cp_commit() {
    asm volatile("cp.async.commit_group;" ::: "memory");
}
template <int N>
__device__ __forceinline__ void cp_wait() {
    asm volatile("cp.async.wait_group %0;" :: "n"(N) : "memory");
}
__device__ __forceinline__ void ldsm4(uint32_t addr, uint32_t r[4]) {
    asm volatile("ldmatrix.sync.aligned.m8n8.x4.shared.b16 {%0,%1,%2,%3}, [%4];"
                 : "=r"(r[0]), "=r"(r[1]), "=r"(r[2]), "=r"(r[3]) : "r"(addr));
}
__device__ __forceinline__ void ldsm4t(uint32_t addr, uint32_t r[4]) {
    asm volatile("ldmatrix.sync.aligned.m8n8.x4.trans.shared.b16 {%0,%1,%2,%3}, [%4];"
                 : "=r"(r[0]), "=r"(r[1]), "=r"(r[2]), "=r"(r[3]) : "r"(addr));
}
__device__ __forceinline__ void mma16816(float c[4], const uint32_t a[4],
                                         const uint32_t b0, const uint32_t b1) {
    asm volatile(
        "mma.sync.aligned.m16n8k16.row.col.f32.f16.f16.f32 "
        "{%0,%1,%2,%3}, {%4,%5,%6,%7}, {%8,%9}, {%0,%1,%2,%3};"
        : "+f"(c[0]), "+f"(c[1]), "+f"(c[2]), "+f"(c[3])
        : "r"(a[0]), "r"(a[1]), "r"(a[2]), "r"(a[3]), "r"(b0), "r"(b1));
}
__device__ __forceinline__ uint32_t pack_h2(float x, float y) {
    __half2 t = __floats2half2_rn(x, y);
    return *reinterpret_cast<uint32_t*>(&t);
}

// ---------------------------------------------------------------------------
// Convert fp32 -> fp16: x
// ---------------------------------------------------------------------------
__global__ void split_x_kernel(const float4* __restrict__ src, int n4)
{
    for (int i = blockIdx.x * blockDim.x + threadIdx.x; i < n4;
         i += gridDim.x * blockDim.x) {
        float4 v = src[i];
        __half2* hp = reinterpret_cast<__half2*>(g_xh + 4 * (size_t)i);
        hp[0] = __floats2half2_rn(v.x, v.y);
        hp[1] = __floats2half2_rn(v.z, v.w);
    }
}

// Fused weight converts (blockIdx.y selects the weight), fp16
__global__ void split_w_kernel(const float4* __restrict__ w0,
                               const float4* __restrict__ w1,
                               const float4* __restrict__ w2,
                               const float4* __restrict__ w3, int n4)
{
    const int which = blockIdx.y;
    const float4* src = (which == 0) ? w0 : (which == 1) ? w1 : (which == 2) ? w2 : w3;
    __half* hi = g_wh[which];

    for (int i = blockIdx.x * blockDim.x + threadIdx.x; i < n4;
         i += gridDim.x * blockDim.x) {
        float4 v = src[i];
        __half2* hp = reinterpret_cast<__half2*>(hi + 4 * (size_t)i);
        hp[0] = __floats2half2_rn(v.x, v.y);
        hp[1] = __floats2half2_rn(v.z, v.w);
    }
}

// ---------------------------------------------------------------------------
// RoPE cos/sin tables: g_ct[d*2048+s], d in [0,64)
// ---------------------------------------------------------------------------
__global__ void rope_tab_kernel()
{
    int i = blockIdx.x * blockDim.x + threadIdx.x;
    if (i >= 64 * S_LEN) return;
    int d = i >> 11, s = i & 2047;
    float invf = (float)exp2(-(double)d * 0.20762050593045952);  // log2(1e4)/64
    float th = (float)s * invf;
    float c, sn;
    sincosf(th, &sn, &c);
    g_ct[i] = c;
    g_st[i] = sn;
}

// ---------------------------------------------------------------------------
// RoPE over g_q, g_k.  Q -> fp16 hi/lo (A side), K -> fp16 hi only (B side).
// ---------------------------------------------------------------------------
__global__ void rope_apply_kernel()
{
    const int total = BATCH * NHEADS * S_LEN * 64;
    int i = blockIdx.x * blockDim.x + threadIdx.x;
    if (i >= total) return;
    int d = i & 63;
    int rs = i >> 6;            // flat (b,h,s)
    int s = rs & 2047;
    size_t base = (size_t)rs * HDIM;
    float c  = g_ct[d * S_LEN + s];
    float sn = g_st[d * S_LEN + s];

    float qlo = g_q[base + d], qhi = g_q[base + d + 64];
    float q0 = qlo * c - qhi * sn;
    float q1 = qhi * c + qlo * sn;
    __half h;
    h = __float2half(q0); g_qhi[base + d] = h;
    g_qlo[base + d] = __float2half(q0 - __half2float(h));
    h = __float2half(q1); g_qhi[base + d + 64] = h;
    g_qlo[base + d + 64] = __float2half(q1 - __half2float(h));

    float klo = g_k[base + d], khi = g_k[base + d + 64];
    g_khi[base + d]      = __float2half(klo * c - khi * sn);
    g_khi[base + d + 64] = __float2half(khi * c + klo * sn);
}

// ---------------------------------------------------------------------------
// HMMA GEMM v7 (fp16, single-product): tile 64x256, BK=64, 8 warps (2m x 4n),
// warp 32x64, 2 CTAs/SM.
// mode: 0=Q(->g_q fp32) 1=K(->g_k fp32) 2=V(->g_vhi fp16) 3=Wo(A=g_atth,->out)
// QKV launch: mode_in = -1 => mode = blockIdx.z.
// smem/stage: A 8K | B 32K = 40KB, 2 stages = 80KB
// ---------------------------------------------------------------------------
#define GM_BM 64
#define GM_BN 256
#define GM_BK 64
#define GM_NIT (DMODEL / GM_BK)          // 32
#define GM_A 0
#define GM_B 8192
#define GM_STAGE 40960
#define GM_SMEM (2 * GM_STAGE)           // 80KB

__device__ __forceinline__ void gm_load_stage(
    uint32_t t0, int kt, int m0, int n0, int tid,
    const __half* __restrict__ Ah, const __half* __restrict__ Bh)
{
    const int k0 = kt * GM_BK;
    #pragma unroll
    for (int i = 0; i < 2; i++) {
        int lin = tid + i * 256;
        int row = lin >> 3, ch = lin & 7;
        uint32_t soff = (uint32_t)(row * 128 + ((ch ^ (row & 7)) << 4));
        size_t ga = (size_t)(m0 + row) * DMODEL + k0 + ch * 8;
        cp16(t0 + GM_A + soff, Ah + ga);
    }
    #pragma unroll
    for (int i = 0; i < 8; i++) {
        int lin = tid + i * 256;
        int row = lin >> 3, ch = lin & 7;
        uint32_t soff = (uint32_t)(row * 128 + ((ch ^ (row & 7)) << 4));
        size_t gb = (size_t)(n0 + row) * DMODEL + k0 + ch * 8;
        cp16(t0 + GM_B + soff, Bh + gb);
    }
}

__global__ __launch_bounds__(256, 2)
void gemm_hmma(float* __restrict__ Dout, int mode_in)
{
    extern __shared__ char smraw[];
    const uint32_t sbase = (uint32_t)__cvta_generic_to_shared(smraw);
    const int tid  = threadIdx.x;
    const int warp = tid >> 5;
    const int lane = tid & 31;
    const int m0 = blockIdx.y * GM_BM;
    const int n0 = blockIdx.x * GM_BN;
    const int mode = (mode_in < 0) ? (int)blockIdx.z : mode_in;

    const __half* Ah = (mode == 3) ? g_atth : g_xh;
    const __half* Bh = g_wh[mode];

    const int wm = warp & 1;        // 0..1
    const int wn = warp >> 1;       // 0..3
    const int quad = lane >> 3;
    const int lr   = lane & 7;

    int arow[2];
    #pragma unroll
    for (int i = 0; i < 2; i++) arow[i] = wm * 32 + i * 16 + (quad & 1) * 8 + lr;
    const int aqp = quad >> 1;
    int brow[4];
    #pragma unroll
    for (int j = 0; j < 4; j++) brow[j] = wn * 64 + j * 16 + (quad >> 1) * 8 + lr;
    const int bqp = quad & 1;

    float c[2][8][4];
    #pragma unroll
    for (int i = 0; i < 2; i++)
        #pragma unroll
        for (int j = 0; j < 8; j++)
            #pragma unroll
            for (int e = 0; e < 4; e++) c[i][j][e] = 0.f;

    gm_load_stage(sbase, 0, m0, n0, tid, Ah, Bh);
    cp_commit();

    #pragma unroll 1
    for (int kt = 0; kt < GM_NIT; kt++) {
        if (kt + 1 < GM_NIT) {
            gm_load_stage(sbase + ((kt + 1) & 1) * GM_STAGE, kt + 1,
                          m0, n0, tid, Ah, Bh);
            cp_commit();
            cp_wait<1>();
        } else {
            cp_wait<0>();
        }
        __syncthreads();

        const uint32_t t0 = sbase + (kt & 1) * GM_STAGE;
        #pragma unroll
        for (int s = 0; s < 4; s++) {
            uint32_t ah[2][4];
            #pragma unroll
            for (int i = 0; i < 2; i++) {
                uint32_t off = (uint32_t)(arow[i] * 128 +
                               (((s * 2 + aqp) ^ (arow[i] & 7)) << 4));
                ldsm4(t0 + GM_A + off, ah[i]);
            }
            uint32_t bh[8][2];
            #pragma unroll
            for (int j2 = 0; j2 < 4; j2++) {
                uint32_t off = (uint32_t)(brow[j2] * 128 +
                               (((s * 2 + bqp) ^ (brow[j2] & 7)) << 4));
                uint32_t t[4];
                ldsm4(t0 + GM_B + off, t);
                bh[2*j2][0] = t[0]; bh[2*j2][1] = t[1];
                bh[2*j2+1][0] = t[2]; bh[2*j2+1][1] = t[3];
            }
            #pragma unroll
            for (int i = 0; i < 2; i++)
                #pragma unroll
                for (int j = 0; j < 8; j++)
                    mma16816(c[i][j], ah[i], bh[j][0], bh[j][1]);
        }
        __syncthreads();
    }

    // ---------------- epilogue ----------------
    #pragma unroll
    for (int i = 0; i < 2; i++) {
        int r0 = m0 + wm * 32 + i * 16 + (lane >> 2);
        #pragma unroll
        for (int half = 0; half < 2; half++) {
            int r = r0 + half * 8;
            int bb = r >> 11, ss = r & 2047;
            #pragma unroll
            for (int j = 0; j < 8; j++) {
                int col = n0 + wn * 64 + j * 8 + (lane & 3) * 2;
                float2 v2 = make_float2(c[i][j][half * 2], c[i][j][half * 2 + 1]);
                if (mode <= 1) {
                    float* outp = (mode == 0) ? g_q : g_k;
                    int h = col >> 7, d = col & 127;
                    size_t base = (((size_t)bb * NHEADS + h) * S_LEN + ss) * HDIM + d;
                    *(float2*)(outp + base) = v2;
                } else if (mode == 2) {
                    int h = col >> 7, d = col & 127;
                    size_t base = (((size_t)bb * NHEADS + h) * S_LEN + ss) * HDIM + d;
                    *(__half2*)(g_vhi + base) = __floats2half2_rn(v2.x, v2.y);
                } else {
                    *(float2*)(Dout + (size_t)r * DMODEL + col) = v2;
                }
            }
        }
    }
}

// ---------------------------------------------------------------------------
// HMMA flash attention (causal, fp16). QK: Q hi+lo (2 products, storage
// split). PV: P hi only. CTA = 128 q rows x 64-key tiles, 8 warps.
// smem: Qhi 32K | Qlo 32K | 2 stages x (Khi 16K | Vhi 16K) = 128KB
// ---------------------------------------------------------------------------
#define FQHI 0
#define FQLO 32768
#define FSTG(s) (65536 + (s) * 32768)
#define FKHI 0
#define FVHI 16384
#define FA_SMEM (65536 + 2 * 32768)   // 128KB

__device__ __forceinline__ uint32_t fswz(int row, int ch) {
    return (uint32_t)(row * 256 + ((ch >> 3) << 7) + (((ch & 7) ^ (row & 7)) << 4));
}

__global__ __launch_bounds__(256, 1)
void flash_hmma()
{
    extern __shared__ char smraw[];
    const uint32_t sb = (uint32_t)__cvta_generic_to_shared(smraw);
    const int tid  = threadIdx.x;
    const int w    = tid >> 5;
    const int lane = tid & 31;
    const int quad = lane >> 3;
    const int lr   = lane & 7;
    const int qt = 15 - blockIdx.x;        // heavy CTAs first
    const int bh = blockIdx.y;

    const __half* qhib = g_qhi + (size_t)bh * S_LEN * HDIM;
    const __half* qlob = g_qlo + (size_t)bh * S_LEN * HDIM;
    const __half* khib = g_khi + (size_t)bh * S_LEN * HDIM;
    const __half* vhib = g_vhi + (size_t)bh * S_LEN * HDIM;

    #pragma unroll
    for (int i = 0; i < 8; i++) {
        int lin = tid + i * 256;
        int row = lin >> 4, ch = lin & 15;
        uint32_t so = fswz(row, ch);
        size_t go = (size_t)(qt * 128 + row) * HDIM + ch * 8;
        cp16(sb + FQHI + so, qhib + go);
        cp16(sb + FQLO + so, qlob + go);
    }
    cp_commit();

    const int nkt = 2 * qt + 2;

    {
        const uint32_t t0 = sb + FSTG(0);
        #pragma unroll
        for (int i = 0; i < 4; i++) {
            int lin = tid + i * 256;
            int row = lin >> 4, ch = lin & 15;
            uint32_t so = fswz(row, ch);
            size_t go = (size_t)row * HDIM + ch * 8;
            cp16(t0 + FKHI + so, khib + go);
            cp16(t0 + FVHI + so, vhib + go);
        }
        cp_commit();
    }

    float o[16][4];
    #pragma unroll
    for (int i = 0; i < 16; i++)
        #pragma unroll
        for (int e = 0; e < 4; e++) o[i][e] = 0.f;
    float mi[2] = {-CUDART_INF_F, -CUDART_INF_F};
    float li[2] = {0.f, 0.f};

    const float scale = 0.08838834764831845f;
    const int ar  = 16 * w + (quad & 1) * 8 + lr;
    const int aqp = quad >> 1;
    const int krb = (quad >> 1) * 8 + lr;
    const int bqp = quad & 1;
    const int vrb = (quad & 1) * 8 + lr;
    const int vqp = quad >> 1;

    #pragma unroll 1
    for (int kt = 0; kt < nkt; kt++) {
        if (kt + 1 < nkt) {
            const uint32_t t0 = sb + FSTG((kt + 1) & 1);
            #pragma unroll
            for (int i = 0; i < 4; i++) {
                int lin = tid + i * 256;
                int row = lin >> 4, ch = lin & 15;
                uint32_t so = fswz(row, ch);
                size_t go = (size_t)((kt + 1) * 64 + row) * HDIM + ch * 8;
                cp16(t0 + FKHI + so, khib + go);
                cp16(t0 + FVHI + so, vhib + go);
            }
            cp_commit();
            cp_wait<1>();
        } else {
            cp_wait<0>();
        }
        __syncthreads();

        const uint32_t stg = sb + FSTG(kt & 1);

        float sc[8][4];
        #pragma unroll
        for (int i = 0; i < 8; i++)
            #pragma unroll
            for (int e = 0; e < 4; e++) sc[i][e] = 0.f;

        #pragma unroll
        for (int s = 0; s < 8; s++) {
            uint32_t qh[4], ql[4];
            uint32_t ao = fswz(ar, s * 2 + aqp);
            ldsm4(sb + FQHI + ao, qh);
            ldsm4(sb + FQLO + ao, ql);
            #pragma unroll
            for (int j2 = 0; j2 < 4; j2++) {
                uint32_t bo = fswz(j2 * 16 + krb, s * 2 + bqp);
                uint32_t th[4];
                ldsm4(stg + FKHI + bo, th);
                mma16816(sc[2*j2],   qh, th[0], th[1]);
                mma16816(sc[2*j2],   ql, th[0], th[1]);
                mma16816(sc[2*j2+1], qh, th[2], th[3]);
                mma16816(sc[2*j2+1], ql, th[2], th[3]);
            }
        }

        const bool needmask = (kt * 64 + 63 > qt * 128 + 16 * w);
        const int rbase = qt * 128 + 16 * w + (lane >> 2);
        #pragma unroll
        for (int half = 0; half < 2; half++) {
            const int rg = rbase + half * 8;
            float mx = -CUDART_INF_F;
            #pragma unroll
            for (int dj = 0; dj < 8; dj++) {
                #pragma unroll
                for (int e = 0; e < 2; e++) {
                    float v = sc[dj][half * 2 + e] * scale;
                    if (needmask) {
                        int col = kt * 64 + dj * 8 + (lane & 3) * 2 + e;
                        if (col > rg) v = -CUDART_INF_F;
                    }
                    sc[dj][half * 2 + e] = v;
                    mx = fmaxf(mx, v);
                }
            }
            mx = fmaxf(mx, __shfl_xor_sync(0xffffffffu, mx, 1));
            mx = fmaxf(mx, __shfl_xor_sync(0xffffffffu, mx, 2));
            float mnew = fmaxf(mi[half], mx);
            float fct  = __expf(mi[half] - mnew);
            mi[half] = mnew;
            float ssum = 0.f;
            #pragma unroll
            for (int dj = 0; dj < 8; dj++) {
                #pragma unroll
                for (int e = 0; e < 2; e++) {
                    float p = __expf(sc[dj][half * 2 + e] - mnew);
                    sc[dj][half * 2 + e] = p;
                    ssum += p;
                }
            }
            ssum += __shfl_xor_sync(0xffffffffu, ssum, 1);
            ssum += __shfl_xor_sync(0xffffffffu, ssum, 2);
            li[half] = li[half] * fct + ssum;
            #pragma unroll
            for (int dt = 0; dt < 16; dt++) {
                o[dt][half * 2]     *= fct;
                o[dt][half * 2 + 1] *= fct;
            }
        }

        #pragma unroll
        for (int t = 0; t < 4; t++) {
            uint32_t ph[4];
            #pragma unroll
            for (int pair = 0; pair < 2; pair++) {
                const float* sp = sc[2 * t + pair];
                ph[pair * 2 + 0] = pack_h2(sp[0], sp[1]);
                ph[pair * 2 + 1] = pack_h2(sp[2], sp[3]);
            }
            #pragma unroll
            for (int j2 = 0; j2 < 8; j2++) {
                uint32_t vo = fswz(t * 16 + vrb, j2 * 2 + vqp);
                uint32_t vh[4];
                ldsm4t(stg + FVHI + vo, vh);
                mma16816(o[2*j2],   ph, vh[0], vh[1]);
                mma16816(o[2*j2+1], ph, vh[2], vh[3]);
            }
        }
        __syncthreads();
    }

    const int b  = bh >> 4;
    const int hh = bh & 15;
    const float inva = 1.0f / li[0];
    const float invb = 1.0f / li[1];
    const int sa = qt * 128 + 16 * w + (lane >> 2);

    #pragma unroll
    for (int dj = 0; dj < 16; dj++) {
        int col = hh * HDIM + dj * 8 + (lane & 3) * 2;
        size_t ia = ((size_t)b * S_LEN + sa) * DMODEL + col;
        size_t ib = ((size_t)b * S_LEN + sa + 8) * DMODEL + col;
        *(__half2*)(g_atth + ia) = __floats2half2_rn(o[dj][0] * inva, o[dj][1] * inva);
        *(__half2*)(g_atth + ib) = __floats2half2_rn(o[dj][2] * invb, o[dj][3] * invb);
    }
}

// ---------------------------------------------------------------------------
// Launch
// ---------------------------------------------------------------------------
extern "C" void kernel_launch(void* const* d_in, const int* in_sizes, int n_in,
                              void* d_out, int out_size)
{
    const float* x  = (const float*)d_in[0];
    const float* Wq = (const float*)d_in[1];
    const float* Wk = (const float*)d_in[2];
    const float* Wv = (const float*)d_in[3];
    const float* Wo = (const float*)d_in[4];
    float* out = (float*)d_out;

    int n4x = MROWS * DMODEL / 4;
    int n4w = DMODEL * DMODEL / 4;
    split_x_kernel<<<2048, 256>>>((const float4*)x, n4x);
    split_w_kernel<<<dim3(1024, 4), 256>>>((const float4*)Wq, (const float4*)Wk,
                                           (const float4*)Wv, (const float4*)Wo, n4w);
    rope_tab_kernel<<<(64 * S_LEN + 255) / 256, 256>>>();

    cudaFuncSetAttribute(gemm_hmma,
                         cudaFuncAttributeMaxDynamicSharedMemorySize, GM_SMEM);

    dim3 gblk(DMODEL / GM_BN, MROWS / GM_BM);       // 8 x 128

    // fused Q/K/V projections (all single-product): blockIdx.z = mode
    gemm_hmma<<<dim3(gblk.x, gblk.y, 3), 256, GM_SMEM>>>(nullptr, -1);

    rope_apply_kernel<<<(BATCH * NHEADS * S_LEN * 64 + 255) / 256, 256>>>();

    cudaFuncSetAttribute(flash_hmma, cudaFuncAttributeMaxDynamicSharedMemorySize, FA_SMEM);
    flash_hmma<<<dim3(16, BATCH * NHEADS), 256, FA_SMEM>>>();

    gemm_hmma<<<gblk, 256, GM_SMEM>>>(out, 3);   // output projection (1-product)
}

// round 11
// speedup vs baseline: 2.4205x; 1.0392x over previous
#include <cuda_runtime.h>
#include <cuda_fp16.h>
#include <math_constants.h>
#include <cstdint>

// Problem constants
#define S_LEN   2048
#define DMODEL  2048
#define NHEADS  16
#define HDIM    128
#define BATCH   4
#define MROWS   (BATCH * S_LEN)   // 8192

// ---------------------------------------------------------------------------
// Scratch (device globals; no allocation in kernel_launch)
// ---------------------------------------------------------------------------
__device__ __half g_xh[(size_t)MROWS * DMODEL];                // x, fp16
__device__ __half g_wh[4][(size_t)DMODEL * DMODEL];            // weights, fp16
__device__ float g_q[(size_t)BATCH * NHEADS * S_LEN * HDIM];   // [B,H,S,hd] pre-RoPE
__device__ float g_k[(size_t)BATCH * NHEADS * S_LEN * HDIM];
__device__ __half g_qhi[(size_t)BATCH * NHEADS * S_LEN * HDIM];
__device__ __half g_qlo[(size_t)BATCH * NHEADS * S_LEN * HDIM];
__device__ __half g_khi[(size_t)BATCH * NHEADS * S_LEN * HDIM];
__device__ __half g_vhi[(size_t)BATCH * NHEADS * S_LEN * HDIM];
__device__ __half g_atth[(size_t)MROWS * DMODEL];              // [B,S,D]
__device__ float g_ct[64 * S_LEN];                              // cos[d][s]
__device__ float g_st[64 * S_LEN];                              // sin[d][s]

// ---------------------------------------------------------------------------
// PTX helpers
// ---------------------------------------------------------------------------
__device__ __forceinline__ void cp16(uint32_t smem_dst, const void* gptr) {
    asm volatile("cp.async.cg.shared.global [%0], [%1], 16;"
                 :: "r"(smem_dst), "l"(__cvta_generic_to_global(gptr)) : "memory");
}
__device__ __forceinline__ void cp_commit() {
    asm volatile("cp.async.commit_group;" ::: "memory");
}
template <int N>
__device__ __forceinline__ void cp_wait() {
    asm volatile("cp.async.wait_group %0;" :: "n"(N) : "memory");
}
__device__ __forceinline__ void ldsm4(uint32_t addr, uint32_t r[4]) {
    asm volatile("ldmatrix.sync.aligned.m8n8.x4.shared.b16 {%0,%1,%2,%3}, [%4];"
                 : "=r"(r[0]), "=r"(r[1]), "=r"(r[2]), "=r"(r[3]) : "r"(addr));
}
__device__ __forceinline__ void ldsm4t(uint32_t addr, uint32_t r[4]) {
    asm volatile("ldmatrix.sync.aligned.m8n8.x4.trans.shared.b16 {%0,%1,%2,%3}, [%4];"
                 : "=r"(r[0]), "=r"(r[1]), "=r"(r[2]), "=r"(r[3]) : "r"(addr));
}
__device__ __forceinline__ void mma16816(float c[4], const uint32_t a[4],
                                         const uint32_t b0, const uint32_t b1) {
    asm volatile(
        "mma.sync.aligned.m16n8k16.row.col.f32.f16.f16.f32 "
        "{%0,%1,%2,%3}, {%4,%5,%6,%7}, {%8,%9}, {%0,%1,%2,%3};"
        : "+f"(c[0]), "+f"(c[1]), "+f"(c[2]), "+f"(c[3])
        : "r"(a[0]), "r"(a[1]), "r"(a[2]), "r"(a[3]), "r"(b0), "r"(b1));
}
__device__ __forceinline__ uint32_t pack_h2(float x, float y) {
    __half2 t = __floats2half2_rn(x, y);
    return *reinterpret_cast<uint32_t*>(&t);
}

// ---------------------------------------------------------------------------
// Fused fp32 -> fp16 converts: y = 0 -> x, y = 1..4 -> Wq/Wk/Wv/Wo
// ---------------------------------------------------------------------------
__global__ void convert_all_kernel(const float4* __restrict__ x,
                                   const float4* __restrict__ w0,
                                   const float4* __restrict__ w1,
                                   const float4* __restrict__ w2,
                                   const float4* __restrict__ w3,
                                   int n4x, int n4w)
{
    const int which = blockIdx.y;
    const float4* src;
    __half* dst;
    int n4;
    if (which == 0)      { src = x;  dst = g_xh;    n4 = n4x; }
    else if (which == 1) { src = w0; dst = g_wh[0]; n4 = n4w; }
    else if (which == 2) { src = w1; dst = g_wh[1]; n4 = n4w; }
    else if (which == 3) { src = w2; dst = g_wh[2]; n4 = n4w; }
    else                 { src = w3; dst = g_wh[3]; n4 = n4w; }

    for (int i = blockIdx.x * blockDim.x + threadIdx.x; i < n4;
         i += gridDim.x * blockDim.x) {
        float4 v = src[i];
        __half2* hp = reinterpret_cast<__half2*>(dst + 4 * (size_t)i);
        hp[0] = __floats2half2_rn(v.x, v.y);
        hp[1] = __floats2half2_rn(v.z, v.w);
    }
}

// ---------------------------------------------------------------------------
// RoPE cos/sin tables: g_ct[d*2048+s], d in [0,64)
// ---------------------------------------------------------------------------
__global__ void rope_tab_kernel()
{
    int i = blockIdx.x * blockDim.x + threadIdx.x;
    if (i >= 64 * S_LEN) return;
    int d = i >> 11, s = i & 2047;
    float invf = (float)exp2(-(double)d * 0.20762050593045952);  // log2(1e4)/64
    float th = (float)s * invf;
    float c, sn;
    sincosf(th, &sn, &c);
    g_ct[i] = c;
    g_st[i] = sn;
}

// ---------------------------------------------------------------------------
// RoPE over g_q, g_k.  Q -> fp16 hi/lo (A side), K -> fp16 hi only (B side).
// ---------------------------------------------------------------------------
__global__ void rope_apply_kernel()
{
    const int total = BATCH * NHEADS * S_LEN * 64;
    int i = blockIdx.x * blockDim.x + threadIdx.x;
    if (i >= total) return;
    int d = i & 63;
    int rs = i >> 6;            // flat (b,h,s)
    int s = rs & 2047;
    size_t base = (size_t)rs * HDIM;
    float c  = g_ct[d * S_LEN + s];
    float sn = g_st[d * S_LEN + s];

    float qlo = g_q[base + d], qhi = g_q[base + d + 64];
    float q0 = qlo * c - qhi * sn;
    float q1 = qhi * c + qlo * sn;
    __half h;
    h = __float2half(q0); g_qhi[base + d] = h;
    g_qlo[base + d] = __float2half(q0 - __half2float(h));
    h = __float2half(q1); g_qhi[base + d + 64] = h;
    g_qlo[base + d + 64] = __float2half(q1 - __half2float(h));

    float klo = g_k[base + d], khi = g_k[base + d + 64];
    g_khi[base + d]      = __float2half(klo * c - khi * sn);
    g_khi[base + d + 64] = __float2half(khi * c + klo * sn);
}

// ---------------------------------------------------------------------------
// HMMA GEMM (fp16, single-product): tile 64x256, BK=64, 8 warps (2m x 4n),
// warp 32x64, 2 CTAs/SM.
// mode: 0=Q(->g_q fp32) 1=K(->g_k fp32) 2=V(->g_vhi fp16) 3=Wo(A=g_atth,->out)
// QKV launch: mode_in = -1 => mode = blockIdx.z.
// smem/stage: A 8K | B 32K = 40KB, 2 stages = 80KB
// ---------------------------------------------------------------------------
#define GM_BM 64
#define GM_BN 256
#define GM_BK 64
#define GM_NIT (DMODEL / GM_BK)          // 32
#define GM_A 0
#define GM_B 8192
#define GM_STAGE 40960
#define GM_SMEM (2 * GM_STAGE)           // 80KB

__device__ __forceinline__ void gm_load_stage(
    uint32_t t0, int kt, int m0, int n0, int tid,
    const __half* __restrict__ Ah, const __half* __restrict__ Bh)
{
    const int k0 = kt * GM_BK;
    #pragma unroll
    for (int i = 0; i < 2; i++) {
        int lin = tid + i * 256;
        int row = lin >> 3, ch = lin & 7;
        uint32_t soff = (uint32_t)(row * 128 + ((ch ^ (row & 7)) << 4));
        size_t ga = (size_t)(m0 + row) * DMODEL + k0 + ch * 8;
        cp16(t0 + GM_A + soff, Ah + ga);
    }
    #pragma unroll
    for (int i = 0; i < 8; i++) {
        int lin = tid + i * 256;
        int row = lin >> 3, ch = lin & 7;
        uint32_t soff = (uint32_t)(row * 128 + ((ch ^ (row & 7)) << 4));
        size_t gb = (size_t)(n0 + row) * DMODEL + k0 + ch * 8;
        cp16(t0 + GM_B + soff, Bh + gb);
    }
}

__global__ __launch_bounds__(256, 2)
void gemm_hmma(float* __restrict__ Dout, int mode_in)
{
    extern __shared__ char smraw[];
    const uint32_t sbase = (uint32_t)__cvta_generic_to_shared(smraw);
    const int tid  = threadIdx.x;
    const int warp = tid >> 5;
    const int lane = tid & 31;
    const int m0 = blockIdx.y * GM_BM;
    const int n0 = blockIdx.x * GM_BN;
    const int mode = (mode_in < 0) ? (int)blockIdx.z : mode_in;

    const __half* Ah = (mode == 3) ? g_atth : g_xh;
    const __half* Bh = g_wh[mode];

    const int wm = warp & 1;        // 0..1
    const int wn = warp >> 1;       // 0..3
    const int quad = lane >> 3;
    const int lr   = lane & 7;

    int arow[2];
    #pragma unroll
    for (int i = 0; i < 2; i++) arow[i] = wm * 32 + i * 16 + (quad & 1) * 8 + lr;
    const int aqp = quad >> 1;
    int brow[4];
    #pragma unroll
    for (int j = 0; j < 4; j++) brow[j] = wn * 64 + j * 16 + (quad >> 1) * 8 + lr;
    const int bqp = quad & 1;

    float c[2][8][4];
    #pragma unroll
    for (int i = 0; i < 2; i++)
        #pragma unroll
        for (int j = 0; j < 8; j++)
            #pragma unroll
            for (int e = 0; e < 4; e++) c[i][j][e] = 0.f;

    gm_load_stage(sbase, 0, m0, n0, tid, Ah, Bh);
    cp_commit();

    #pragma unroll 1
    for (int kt = 0; kt < GM_NIT; kt++) {
        if (kt + 1 < GM_NIT) {
            gm_load_stage(sbase + ((kt + 1) & 1) * GM_STAGE, kt + 1,
                          m0, n0, tid, Ah, Bh);
            cp_commit();
            cp_wait<1>();
        } else {
            cp_wait<0>();
        }
        __syncthreads();

        const uint32_t t0 = sbase + (kt & 1) * GM_STAGE;
        #pragma unroll
        for (int s = 0; s < 4; s++) {
            uint32_t ah[2][4];
            #pragma unroll
            for (int i = 0; i < 2; i++) {
                uint32_t off = (uint32_t)(arow[i] * 128 +
                               (((s * 2 + aqp) ^ (arow[i] & 7)) << 4));
                ldsm4(t0 + GM_A + off, ah[i]);
            }
            uint32_t bh[8][2];
            #pragma unroll
            for (int j2 = 0; j2 < 4; j2++) {
                uint32_t off = (uint32_t)(brow[j2] * 128 +
                               (((s * 2 + bqp) ^ (brow[j2] & 7)) << 4));
                uint32_t t[4];
                ldsm4(t0 + GM_B + off, t);
                bh[2*j2][0] = t[0]; bh[2*j2][1] = t[1];
                bh[2*j2+1][0] = t[2]; bh[2*j2+1][1] = t[3];
            }
            #pragma unroll
            for (int i = 0; i < 2; i++)
                #pragma unroll
                for (int j = 0; j < 8; j++)
                    mma16816(c[i][j], ah[i], bh[j][0], bh[j][1]);
        }
        __syncthreads();
    }

    // ---------------- epilogue ----------------
    #pragma unroll
    for (int i = 0; i < 2; i++) {
        int r0 = m0 + wm * 32 + i * 16 + (lane >> 2);
        #pragma unroll
        for (int half = 0; half < 2; half++) {
            int r = r0 + half * 8;
            int bb = r >> 11, ss = r & 2047;
            #pragma unroll
            for (int j = 0; j < 8; j++) {
                int col = n0 + wn * 64 + j * 8 + (lane & 3) * 2;
                float2 v2 = make_float2(c[i][j][half * 2], c[i][j][half * 2 + 1]);
                if (mode <= 1) {
                    float* outp = (mode == 0) ? g_q : g_k;
                    int h = col >> 7, d = col & 127;
                    size_t base = (((size_t)bb * NHEADS + h) * S_LEN + ss) * HDIM + d;
                    *(float2*)(outp + base) = v2;
                } else if (mode == 2) {
                    int h = col >> 7, d = col & 127;
                    size_t base = (((size_t)bb * NHEADS + h) * S_LEN + ss) * HDIM + d;
                    *(__half2*)(g_vhi + base) = __floats2half2_rn(v2.x, v2.y);
                } else {
                    *(float2*)(Dout + (size_t)r * DMODEL + col) = v2;
                }
            }
        }
    }
}

// ---------------------------------------------------------------------------
// HMMA flash attention (causal, fp16), v2: CTA = 64 q rows x 64-key tiles,
// 4 warps (128 thr), warp = 16 q rows x all 64 keys, 2 CTAs/SM.
// QK: Q hi+lo (2 products). PV: P hi only.
// smem: Qhi 16K | Qlo 16K | 2 stages x (Khi 16K | Vhi 16K) = 96KB
// ---------------------------------------------------------------------------
#define FA_BM 64
#define FQHI 0
#define FQLO 16384
#define FSTG(s) (32768 + (s) * 32768)
#define FKHI 0
#define FVHI 16384
#define FA_SMEM (32768 + 2 * 32768)   // 96KB

__device__ __forceinline__ uint32_t fswz(int row, int ch) {
    return (uint32_t)(row * 256 + ((ch >> 3) << 7) + (((ch & 7) ^ (row & 7)) << 4));
}

__global__ __launch_bounds__(128, 2)
void flash_hmma()
{
    extern __shared__ char smraw[];
    const uint32_t sb = (uint32_t)__cvta_generic_to_shared(smraw);
    const int tid  = threadIdx.x;
    const int w    = tid >> 5;           // 0..3
    const int lane = tid & 31;
    const int quad = lane >> 3;
    const int lr   = lane & 7;
    const int qt = 31 - blockIdx.x;      // heavy CTAs first, 64-row tiles
    const int bh = blockIdx.y;

    const __half* qhib = g_qhi + (size_t)bh * S_LEN * HDIM;
    const __half* qlob = g_qlo + (size_t)bh * S_LEN * HDIM;
    const __half* khib = g_khi + (size_t)bh * S_LEN * HDIM;
    const __half* vhib = g_vhi + (size_t)bh * S_LEN * HDIM;

    // Q tile: 64 rows x 16 chunks (hi + lo), 128 threads x 8 iters
    #pragma unroll
    for (int i = 0; i < 8; i++) {
        int lin = tid + i * 128;
        int row = lin >> 4, ch = lin & 15;
        uint32_t so = fswz(row, ch);
        size_t go = (size_t)(qt * FA_BM + row) * HDIM + ch * 8;
        cp16(sb + FQHI + so, qhib + go);
        cp16(sb + FQLO + so, qlob + go);
    }
    cp_commit();

    const int nkt = qt + 1;

    {
        const uint32_t t0 = sb + FSTG(0);
        #pragma unroll
        for (int i = 0; i < 8; i++) {
            int lin = tid + i * 128;
            int row = lin >> 4, ch = lin & 15;
            uint32_t so = fswz(row, ch);
            size_t go = (size_t)row * HDIM + ch * 8;
            cp16(t0 + FKHI + so, khib + go);
            cp16(t0 + FVHI + so, vhib + go);
        }
        cp_commit();
    }

    float o[16][4];
    #pragma unroll
    for (int i = 0; i < 16; i++)
        #pragma unroll
        for (int e = 0; e < 4; e++) o[i][e] = 0.f;
    float mi[2] = {-CUDART_INF_F, -CUDART_INF_F};
    float li[2] = {0.f, 0.f};

    const float scale = 0.08838834764831845f;
    const int ar  = 16 * w + (quad & 1) * 8 + lr;
    const int aqp = quad >> 1;
    const int krb = (quad >> 1) * 8 + lr;
    const int bqp = quad & 1;
    const int vrb = (quad & 1) * 8 + lr;
    const int vqp = quad >> 1;

    #pragma unroll 1
    for (int kt = 0; kt < nkt; kt++) {
        if (kt + 1 < nkt) {
            const uint32_t t0 = sb + FSTG((kt + 1) & 1);
            #pragma unroll
            for (int i = 0; i < 8; i++) {
                int lin = tid + i * 128;
                int row = lin >> 4, ch = lin & 15;
                uint32_t so = fswz(row, ch);
                size_t go = (size_t)((kt + 1) * 64 + row) * HDIM + ch * 8;
                cp16(t0 + FKHI + so, khib + go);
                cp16(t0 + FVHI + so, vhib + go);
            }
            cp_commit();
            cp_wait<1>();
        } else {
            cp_wait<0>();
        }
        __syncthreads();

        const uint32_t stg = sb + FSTG(kt & 1);

        float sc[8][4];
        #pragma unroll
        for (int i = 0; i < 8; i++)
            #pragma unroll
            for (int e = 0; e < 4; e++) sc[i][e] = 0.f;

        #pragma unroll
        for (int s = 0; s < 8; s++) {
            uint32_t qh[4], ql[4];
            uint32_t ao = fswz(ar, s * 2 + aqp);
            ldsm4(sb + FQHI + ao, qh);
            ldsm4(sb + FQLO + ao, ql);
            #pragma unroll
            for (int j2 = 0; j2 < 4; j2++) {
                uint32_t bo = fswz(j2 * 16 + krb, s * 2 + bqp);
                uint32_t th[4];
                ldsm4(stg + FKHI + bo, th);
                mma16816(sc[2*j2],   qh, th[0], th[1]);
                mma16816(sc[2*j2],   ql, th[0], th[1]);
                mma16816(sc[2*j2+1], qh, th[2], th[3]);
                mma16816(sc[2*j2+1], ql, th[2], th[3]);
            }
        }

        const bool needmask = (kt * 64 + 63 > qt * FA_BM + 16 * w);
        const int rbase = qt * FA_BM + 16 * w + (lane >> 2);
        #pragma unroll
        for (int half = 0; half < 2; half++) {
            const int rg = rbase + half * 8;
            float mx = -CUDART_INF_F;
            #pragma unroll
            for (int dj = 0; dj < 8; dj++) {
                #pragma unroll
                for (int e = 0; e < 2; e++) {
                    float v = sc[dj][half * 2 + e] * scale;
                    if (needmask) {
                        int col = kt * 64 + dj * 8 + (lane & 3) * 2 + e;
                        if (col > rg) v = -CUDART_INF_F;
                    }
                    sc[dj][half * 2 + e] = v;
                    mx = fmaxf(mx, v);
                }
            }
            mx = fmaxf(mx, __shfl_xor_sync(0xffffffffu, mx, 1));
            mx = fmaxf(mx, __shfl_xor_sync(0xffffffffu, mx, 2));
            float mnew = fmaxf(mi[half], mx);
            float fct  = __expf(mi[half] - mnew);
            mi[half] = mnew;
            float ssum = 0.f;
            #pragma unroll
            for (int dj = 0; dj < 8; dj++) {
                #pragma unroll
                for (int e = 0; e < 2; e++) {
                    float p = __expf(sc[dj][half * 2 + e] - mnew);
                    sc[dj][half * 2 + e] = p;
                    ssum += p;
                }
            }
            ssum += __shfl_xor_sync(0xffffffffu, ssum, 1);
            ssum += __shfl_xor_sync(0xffffffffu, ssum, 2);
            li[half] = li[half] * fct + ssum;
            #pragma unroll
            for (int dt = 0; dt < 16; dt++) {
                o[dt][half * 2]     *= fct;
                o[dt][half * 2 + 1] *= fct;
            }
        }

        #pragma unroll
        for (int t = 0; t < 4; t++) {
            uint32_t ph[4];
            #pragma unroll
            for (int pair = 0; pair < 2; pair++) {
                const float* sp = sc[2 * t + pair];
                ph[pair * 2 + 0] = pack_h2(sp[0], sp[1]);
                ph[pair * 2 + 1] = pack_h2(sp[2], sp[3]);
            }
            #pragma unroll
            for (int j2 = 0; j2 < 8; j2++) {
                uint32_t vo = fswz(t * 16 + vrb, j2 * 2 + vqp);
                uint32_t vh[4];
                ldsm4t(stg + FVHI + vo, vh);
                mma16816(o[2*j2],   ph, vh[0], vh[1]);
                mma16816(o[2*j2+1], ph, vh[2], vh[3]);
            }
        }
        __syncthreads();
    }

    const int b  = bh >> 4;
    const int hh = bh & 15;
    const float inva = 1.0f / li[0];
    const float invb = 1.0f / li[1];
    const int sa = qt * FA_BM + 16 * w + (lane >> 2);

    #pragma unroll
    for (int dj = 0; dj < 16; dj++) {
        int col = hh * HDIM + dj * 8 + (lane & 3) * 2;
        size_t ia = ((size_t)b * S_LEN + sa) * DMODEL + col;
        size_t ib = ((size_t)b * S_LEN + sa + 8) * DMODEL + col;
        *(__half2*)(g_atth + ia) = __floats2half2_rn(o[dj][0] * inva, o[dj][1] * inva);
        *(__half2*)(g_atth + ib) = __floats2half2_rn(o[dj][2] * invb, o[dj][3] * invb);
    }
}

// ---------------------------------------------------------------------------
// Launch
// ---------------------------------------------------------------------------
extern "C" void kernel_launch(void* const* d_in, const int* in_sizes, int n_in,
                              void* d_out, int out_size)
{
    const float* x  = (const float*)d_in[0];
    const float* Wq = (const float*)d_in[1];
    const float* Wk = (const float*)d_in[2];
    const float* Wv = (const float*)d_in[3];
    const float* Wo = (const float*)d_in[4];
    float* out = (float*)d_out;

    int n4x = MROWS * DMODEL / 4;
    int n4w = DMODEL * DMODEL / 4;
    convert_all_kernel<<<dim3(1024, 5), 256>>>(
        (const float4*)x, (const float4*)Wq, (const float4*)Wk,
        (const float4*)Wv, (const float4*)Wo, n4x, n4w);
    rope_tab_kernel<<<(64 * S_LEN + 255) / 256, 256>>>();

    cudaFuncSetAttribute(gemm_hmma,
                         cudaFuncAttributeMaxDynamicSharedMemorySize, GM_SMEM);

    dim3 gblk(DMODEL / GM_BN, MROWS / GM_BM);       // 8 x 128

    // fused Q/K/V projections (single-product): blockIdx.z = mode
    gemm_hmma<<<dim3(gblk.x, gblk.y, 3), 256, GM_SMEM>>>(nullptr, -1);

    rope_apply_kernel<<<(BATCH * NHEADS * S_LEN * 64 + 255) / 256, 256>>>();

    cudaFuncSetAttribute(flash_hmma, cudaFuncAttributeMaxDynamicSharedMemorySize, FA_SMEM);
    flash_hmma<<<dim3(32, BATCH * NHEADS), 128, FA_SMEM>>>();

    gemm_hmma<<<gblk, 256, GM_SMEM>>>(out, 3);   // output projection (1-product)
}